// round 3
// baseline (speedup 1.0000x reference)
#include <cuda_runtime.h>
#include <cuda_bf16.h>
#include <math.h>

// ---------------------------------------------------------------------------
// HGT forward, fp32 baseline.
// Sizes fixed per problem spec.
// ---------------------------------------------------------------------------
#define NA     20000
#define NP     40000
#define D      256
#define HH     4
#define DKK    64
#define DOUT   64
#define LL     2
#define E_WB   150000
#define E_W    150000
#define E_C    300000

// ------------------------- device scratch (no runtime alloc allowed) -------
__device__ float g_feats_a[2][NA * D];
__device__ float g_feats_p[2][NP * D];
__device__ float g_q_a[NA * D];
__device__ float g_q_p[NP * D];
__device__ float g_khat_wb[NP * D];
__device__ float g_khat_w [NA * D];
__device__ float g_khat_c [NP * D];
__device__ float g_mhat_wb[NP * D];
__device__ float g_mhat_w [NA * D];
__device__ float g_mhat_c [NP * D];
__device__ float g_agg_a[NA * D];
__device__ float g_agg_p[NP * D];
__device__ float g_tr_a[NA * D];
__device__ float g_tr_p[NP * D];
__device__ float g_Wk[LL * 3 * D * D];
__device__ float g_bk[LL * 3 * D];
__device__ float g_Wm[LL * 3 * D * D];
__device__ float g_bm[LL * 3 * D];

// ---------------------------------------------------------------------------
// Fold per-head w_att / w_msg into the dense K / M projection weights:
//   Wk[l][e][d][h*64+j] = sum_c kW[l][st(e)][d][h*64+c] * w_att[l][e][h][c][j]
//   bk likewise from kb. (same for Wm/bm with mW/w_msg)
// grid = (12, 257): x = l*6 + e*2 + which, y = row d (256 == bias row)
// ---------------------------------------------------------------------------
__global__ void combine_weights(const float* __restrict__ kW, const float* __restrict__ kb,
                                const float* __restrict__ mW, const float* __restrict__ mb,
                                const float* __restrict__ w_att, const float* __restrict__ w_msg,
                                float* __restrict__ Wk, float* __restrict__ bk,
                                float* __restrict__ Wm, float* __restrict__ bm)
{
    int mat = blockIdx.x;
    int l = mat / 6;
    int r6 = mat % 6;
    int e = r6 / 2;
    int which = r6 % 2;         // 0 = k, 1 = m
    int d = blockIdx.y;         // 0..256 (256 == bias row)
    int j = threadIdx.x;        // 0..255
    int h = j >> 6;
    int jj = j & 63;
    int st = (e == 1) ? 0 : 1;  // WRITES(1): src=author(0); CITES(0)/WRITTEN_BY(2): src=paper(1)

    const float* W   = which ? mW : kW;
    const float* B   = which ? mb : kb;
    const float* att = which ? w_msg : w_att;

    const float* wrow;
    if (d < 256) wrow = W + (((size_t)(l * 2 + st) * 256 + d) * 256);
    else         wrow = B + ((size_t)(l * 2 + st) * 256);
    const float* a = att + ((size_t)((l * 3 + e) * 4 + h)) * 64 * 64;

    float s = 0.f;
#pragma unroll 8
    for (int c = 0; c < 64; c++)
        s += wrow[h * 64 + c] * a[c * 64 + jj];

    float* out  = which ? Wm : Wk;
    float* outb = which ? bm : bk;
    if (d < 256) out[((size_t)(l * 3 + e) * 256 + d) * 256 + j] = s;
    else         outb[(size_t)(l * 3 + e) * 256 + j] = s;
}

// ---------------------------------------------------------------------------
// fp32 GEMM: C[M,N] = act( (a_scale*A[M,256]) @ W[256,N] + bias[N] )
// BM=128, BN=64, BK=32, 256 threads, 8x4 outputs per thread.
// ---------------------------------------------------------------------------
__device__ __forceinline__ float gelu_exact(float x) {
    return 0.5f * x * (1.0f + erff(x * 0.70710678118654752f));
}

template <bool GELU>
__global__ void __launch_bounds__(256, 2)
gemm_kernel(const float* __restrict__ A, const float* __restrict__ W,
            const float* __restrict__ bias, float* __restrict__ C,
            int M, int N, float a_scale)
{
    const int BM = 128, BN = 64, BK = 32;
    __shared__ float As[BK][BM + 4];   // transposed A tile, padded
    __shared__ float Bs[BK][BN];

    int tid = threadIdx.x;
    int m0 = blockIdx.x * BM;
    int n0 = blockIdx.y * BN;
    int tr = tid >> 4;          // 0..15
    int tc = tid & 15;          // 0..15

    int a_row = tid >> 3;           // 0..31
    int a_c4  = (tid & 7) * 4;      // 0..28
    int b_row = tid >> 4;           // 0..15
    int b_c4  = (tid & 15) * 4;     // 0..60

    float acc[8][4];
#pragma unroll
    for (int i = 0; i < 8; i++)
#pragma unroll
        for (int j = 0; j < 4; j++) acc[i][j] = 0.f;

    for (int kt = 0; kt < 256; kt += BK) {
        // A tile 128x32 -> As[k][m]
#pragma unroll
        for (int rr = 0; rr < 4; rr++) {
            int row = a_row + rr * 32;
            int grow = m0 + row;
            float4 v = make_float4(0.f, 0.f, 0.f, 0.f);
            if (grow < M) v = *(const float4*)(A + (size_t)grow * 256 + kt + a_c4);
            As[a_c4 + 0][row] = v.x * a_scale;
            As[a_c4 + 1][row] = v.y * a_scale;
            As[a_c4 + 2][row] = v.z * a_scale;
            As[a_c4 + 3][row] = v.w * a_scale;
        }
        // B tile 32xBN
#pragma unroll
        for (int rr = 0; rr < 2; rr++) {
            int row = b_row + rr * 16;
            *(float4*)&Bs[row][b_c4] = *(const float4*)(W + (size_t)(kt + row) * N + n0 + b_c4);
        }
        __syncthreads();

#pragma unroll
        for (int k = 0; k < BK; k++) {
            float4 a0 = *(const float4*)&As[k][tr * 8];
            float4 a1 = *(const float4*)&As[k][tr * 8 + 4];
            float4 b4 = *(const float4*)&Bs[k][tc * 4];
            float av[8] = {a0.x, a0.y, a0.z, a0.w, a1.x, a1.y, a1.z, a1.w};
            float bv[4] = {b4.x, b4.y, b4.z, b4.w};
#pragma unroll
            for (int i = 0; i < 8; i++)
#pragma unroll
                for (int j = 0; j < 4; j++)
                    acc[i][j] += av[i] * bv[j];
        }
        __syncthreads();
    }

    float bv[4];
#pragma unroll
    for (int j = 0; j < 4; j++) bv[j] = bias[n0 + tc * 4 + j];

#pragma unroll
    for (int i = 0; i < 8; i++) {
        int grow = m0 + tr * 8 + i;
        if (grow >= M) break;
        float4 o;
        o.x = acc[i][0] + bv[0];
        o.y = acc[i][1] + bv[1];
        o.z = acc[i][2] + bv[2];
        o.w = acc[i][3] + bv[3];
        if (GELU) {
            o.x = gelu_exact(o.x); o.y = gelu_exact(o.y);
            o.z = gelu_exact(o.z); o.w = gelu_exact(o.w);
        }
        *(float4*)(C + (size_t)grow * N + n0 + tc * 4) = o;
    }
}

// ---------------------------------------------------------------------------
// Edge kernel: one warp per edge.
//   score[h] = <q[dst,h,:], khat[src,h,:]> * pri[h] / 8
//   attn[h]  = sigmoid(score[h]) * ew[e]
//   agg[dst] += mhat[src] * attn   (red.global.add.v4.f32)
// ---------------------------------------------------------------------------
__global__ void edge_kernel(const float* __restrict__ q, const float* __restrict__ khat,
                            const float* __restrict__ mhat,
                            const int* __restrict__ src, const int* __restrict__ dst,
                            const float* __restrict__ ew, const float* __restrict__ pri,
                            float* __restrict__ agg, int E)
{
    int gw = (int)((blockIdx.x * (size_t)blockDim.x + threadIdx.x) >> 5);
    int lane = threadIdx.x & 31;
    if (gw >= E) return;

    int s = src[gw];
    int d = dst[gw];

    const float4* qr = (const float4*)(q    + (size_t)d * 256) + lane * 2;
    const float4* kr = (const float4*)(khat + (size_t)s * 256) + lane * 2;
    float4 q0 = qr[0], q1 = qr[1];
    float4 k0 = kr[0], k1 = kr[1];
    float p = q0.x * k0.x + q0.y * k0.y + q0.z * k0.z + q0.w * k0.w
            + q1.x * k1.x + q1.y * k1.y + q1.z * k1.z + q1.w * k1.w;
    // reduce within each 8-lane head group (each head spans 8 lanes * 8 floats)
    p += __shfl_xor_sync(0xffffffffu, p, 1);
    p += __shfl_xor_sync(0xffffffffu, p, 2);
    p += __shfl_xor_sync(0xffffffffu, p, 4);

    int h = lane >> 3;
    float score = p * pri[h] * 0.125f;                  // / sqrt(64)
    float attn = ew[gw] / (1.f + __expf(-score));

    const float4* mr = (const float4*)(mhat + (size_t)s * 256) + lane * 2;
    float4 m0 = mr[0], m1 = mr[1];

    float* out = agg + (size_t)d * 256 + lane * 8;
    asm volatile("red.global.add.v4.f32 [%0], {%1,%2,%3,%4};" ::
                 "l"(out), "f"(m0.x * attn), "f"(m0.y * attn),
                 "f"(m0.z * attn), "f"(m0.w * attn) : "memory");
    asm volatile("red.global.add.v4.f32 [%0], {%1,%2,%3,%4};" ::
                 "l"(out + 4), "f"(m1.x * attn), "f"(m1.y * attn),
                 "f"(m1.z * attn), "f"(m1.w * attn) : "memory");
}

// ---------------------------------------------------------------------------
// Skip-blend + LayerNorm: one warp per row of 256.
//   alpha = sigmoid(skip[skip_idx]); o = tr*alpha + feats*(1-alpha); LN(o)*g+b
// ---------------------------------------------------------------------------
__global__ void ln_blend_kernel(const float* __restrict__ tr, const float* __restrict__ feats,
                                const float* __restrict__ g, const float* __restrict__ b,
                                const float* __restrict__ skip, int skip_idx,
                                float* __restrict__ out, int N)
{
    int row = (int)((blockIdx.x * (size_t)blockDim.x + threadIdx.x) >> 5);
    int lane = threadIdx.x & 31;
    if (row >= N) return;

    float alpha = 1.f / (1.f + __expf(-skip[skip_idx]));
    float beta = 1.f - alpha;

    const float4* t4 = (const float4*)(tr    + (size_t)row * 256) + lane * 2;
    const float4* f4 = (const float4*)(feats + (size_t)row * 256) + lane * 2;
    float4 ta = t4[0], tb = t4[1], fa = f4[0], fb = f4[1];

    float v[8];
    v[0] = ta.x * alpha + fa.x * beta;
    v[1] = ta.y * alpha + fa.y * beta;
    v[2] = ta.z * alpha + fa.z * beta;
    v[3] = ta.w * alpha + fa.w * beta;
    v[4] = tb.x * alpha + fb.x * beta;
    v[5] = tb.y * alpha + fb.y * beta;
    v[6] = tb.z * alpha + fb.z * beta;
    v[7] = tb.w * alpha + fb.w * beta;

    float s = 0.f;
#pragma unroll
    for (int i = 0; i < 8; i++) s += v[i];
#pragma unroll
    for (int o = 16; o > 0; o >>= 1) s += __shfl_xor_sync(0xffffffffu, s, o);
    float mean = s * (1.f / 256.f);

    float sq = 0.f;
#pragma unroll
    for (int i = 0; i < 8; i++) { float dv = v[i] - mean; sq += dv * dv; }
#pragma unroll
    for (int o = 16; o > 0; o >>= 1) sq += __shfl_xor_sync(0xffffffffu, sq, o);
    float rstd = rsqrtf(sq * (1.f / 256.f) + 1e-5f);

    const float4* g4 = (const float4*)(g) + lane * 2;
    const float4* b4 = (const float4*)(b) + lane * 2;
    float4 ga = g4[0], gb = g4[1], ba = b4[0], bb = b4[1];

    float4 o0, o1;
    o0.x = (v[0] - mean) * rstd * ga.x + ba.x;
    o0.y = (v[1] - mean) * rstd * ga.y + ba.y;
    o0.z = (v[2] - mean) * rstd * ga.z + ba.z;
    o0.w = (v[3] - mean) * rstd * ga.w + ba.w;
    o1.x = (v[4] - mean) * rstd * gb.x + bb.x;
    o1.y = (v[5] - mean) * rstd * gb.y + bb.y;
    o1.z = (v[6] - mean) * rstd * gb.z + bb.z;
    o1.w = (v[7] - mean) * rstd * gb.w + bb.w;

    float4* outp = (float4*)(out + (size_t)row * 256) + lane * 2;
    outp[0] = o0;
    outp[1] = o1;
}

// ---------------------------------------------------------------------------
// Host-side orchestration (graph-capturable: kernels + async memsets only).
// ---------------------------------------------------------------------------
static inline dim3 gemm_grid(int M, int N) { return dim3((M + 127) / 128, N / 64); }

extern "C" void kernel_launch(void* const* d_in, const int* in_sizes, int n_in,
                              void* d_out, int out_size)
{
    const float* x_author = (const float*)d_in[0];
    const float* x_paper  = (const float*)d_in[1];
    const float* ew_wb    = (const float*)d_in[2];
    const float* ew_w     = (const float*)d_in[3];
    const float* ew_c     = (const float*)d_in[4];
    const float* adapt_W  = (const float*)d_in[5];
    const float* adapt_b  = (const float*)d_in[6];
    const float* kW       = (const float*)d_in[7];
    const float* kb       = (const float*)d_in[8];
    const float* qW       = (const float*)d_in[9];
    const float* qb       = (const float*)d_in[10];
    const float* mW       = (const float*)d_in[11];
    const float* mb       = (const float*)d_in[12];
    const float* aW       = (const float*)d_in[13];
    const float* ab       = (const float*)d_in[14];
    const float* w_pri    = (const float*)d_in[15];
    const float* w_att    = (const float*)d_in[16];
    const float* w_msg    = (const float*)d_in[17];
    const float* skip     = (const float*)d_in[18];
    const float* ln_g     = (const float*)d_in[19];
    const float* ln_b     = (const float*)d_in[20];
    const float* out_W    = (const float*)d_in[21];
    const float* out_b    = (const float*)d_in[22];
    const int* src_wb     = (const int*)d_in[23];
    const int* dst_wb     = (const int*)d_in[24];
    const int* src_w      = (const int*)d_in[25];
    const int* dst_w      = (const int*)d_in[26];
    const int* src_c      = (const int*)d_in[27];
    const int* dst_c      = (const int*)d_in[28];
    (void)in_sizes; (void)n_in; (void)out_size;

    float *feats_a, *feats_p, *q_a, *q_p;
    float *khat_wb, *khat_w, *khat_c, *mhat_wb, *mhat_w, *mhat_c;
    float *agg_a, *agg_p, *tr_a, *tr_p, *Wkp, *bkp, *Wmp, *bmp;
#define SYM(var, sym) cudaGetSymbolAddress((void**)&var, sym)
    SYM(feats_a, g_feats_a); SYM(feats_p, g_feats_p);
    SYM(q_a, g_q_a); SYM(q_p, g_q_p);
    SYM(khat_wb, g_khat_wb); SYM(khat_w, g_khat_w); SYM(khat_c, g_khat_c);
    SYM(mhat_wb, g_mhat_wb); SYM(mhat_w, g_mhat_w); SYM(mhat_c, g_mhat_c);
    SYM(agg_a, g_agg_a); SYM(agg_p, g_agg_p);
    SYM(tr_a, g_tr_a); SYM(tr_p, g_tr_p);
    SYM(Wkp, g_Wk); SYM(bkp, g_bk); SYM(Wmp, g_Wm); SYM(bmp, g_bm);
#undef SYM

    // feats ping-pong: layer l reads [l&1], writes [1-(l&1)]
    float* fa[2] = {feats_a, feats_a + (size_t)NA * D};
    float* fp[2] = {feats_p, feats_p + (size_t)NP * D};

    // 0) fold w_att/w_msg into K/M projection weights
    combine_weights<<<dim3(12, 257), 256>>>(kW, kb, mW, mb, w_att, w_msg, Wkp, bkp, Wmp, bmp);

    // 1) adapt + exact GELU
    gemm_kernel<true><<<gemm_grid(NA, D), 256>>>(x_author, adapt_W,           adapt_b,       fa[0], NA, D, 1.f);
    gemm_kernel<true><<<gemm_grid(NP, D), 256>>>(x_paper,  adapt_W + 65536,   adapt_b + 256, fp[0], NP, D, 1.f);

    for (int l = 0; l < LL; l++) {
        int cur = l & 1, nxt = 1 - cur;
        const float* A_a = fa[cur];
        const float* A_p = fp[cur];

        // q bases
        gemm_kernel<false><<<gemm_grid(NA, D), 256>>>(A_a, qW + (size_t)(l * 2 + 0) * 65536, qb + (l * 2 + 0) * 256, q_a, NA, D, 1.f);
        gemm_kernel<false><<<gemm_grid(NP, D), 256>>>(A_p, qW + (size_t)(l * 2 + 1) * 65536, qb + (l * 2 + 1) * 256, q_p, NP, D, 1.f);

        // folded khat / mhat per relation (e: CITES=0, WRITES=1, WRITTEN_BY=2)
        gemm_kernel<false><<<gemm_grid(NP, D), 256>>>(A_p, Wkp + (size_t)(l * 3 + 2) * 65536, bkp + (l * 3 + 2) * 256, khat_wb, NP, D, 1.f);
        gemm_kernel<false><<<gemm_grid(NA, D), 256>>>(A_a, Wkp + (size_t)(l * 3 + 1) * 65536, bkp + (l * 3 + 1) * 256, khat_w,  NA, D, 1.f);
        gemm_kernel<false><<<gemm_grid(NP, D), 256>>>(A_p, Wkp + (size_t)(l * 3 + 0) * 65536, bkp + (l * 3 + 0) * 256, khat_c,  NP, D, 1.f);
        gemm_kernel<false><<<gemm_grid(NP, D), 256>>>(A_p, Wmp + (size_t)(l * 3 + 2) * 65536, bmp + (l * 3 + 2) * 256, mhat_wb, NP, D, 1.f);
        gemm_kernel<false><<<gemm_grid(NA, D), 256>>>(A_a, Wmp + (size_t)(l * 3 + 1) * 65536, bmp + (l * 3 + 1) * 256, mhat_w,  NA, D, 1.f);
        gemm_kernel<false><<<gemm_grid(NP, D), 256>>>(A_p, Wmp + (size_t)(l * 3 + 0) * 65536, bmp + (l * 3 + 0) * 256, mhat_c,  NP, D, 1.f);

        cudaMemsetAsync(agg_a, 0, (size_t)NA * D * sizeof(float), 0);
        cudaMemsetAsync(agg_p, 0, (size_t)NP * D * sizeof(float), 0);

        // edge aggregation (warp per edge)
        edge_kernel<<<(E_WB + 7) / 8, 256>>>(q_a, khat_wb, mhat_wb, src_wb, dst_wb, ew_wb,
                                             w_pri + (l * 3 + 2) * 4, agg_a, E_WB);
        edge_kernel<<<(E_W + 7) / 8, 256>>>(q_p, khat_w, mhat_w, src_w, dst_w, ew_w,
                                            w_pri + (l * 3 + 1) * 4, agg_p, E_W);
        edge_kernel<<<(E_C + 7) / 8, 256>>>(q_p, khat_c, mhat_c, src_c, dst_c, ew_c,
                                            w_pri + (l * 3 + 0) * 4, agg_p, E_C);

        // a-projection (paper gets the 0.5 cross-relation mean folded into a_scale)
        gemm_kernel<false><<<gemm_grid(NA, D), 256>>>(agg_a, aW + (size_t)(l * 2 + 0) * 65536, ab + (l * 2 + 0) * 256, tr_a, NA, D, 1.0f);
        gemm_kernel<false><<<gemm_grid(NP, D), 256>>>(agg_p, aW + (size_t)(l * 2 + 1) * 65536, ab + (l * 2 + 1) * 256, tr_p, NP, D, 0.5f);

        // skip blend + LN
        ln_blend_kernel<<<(NA + 7) / 8, 256>>>(tr_a, A_a, ln_g + (l * 2 + 0) * 256, ln_b + (l * 2 + 0) * 256,
                                               skip, l * 3 + 0, fa[nxt], NA);
        ln_blend_kernel<<<(NP + 7) / 8, 256>>>(tr_p, A_p, ln_g + (l * 2 + 1) * 256, ln_b + (l * 2 + 1) * 256,
                                               skip, l * 3 + 1, fp[nxt], NP);
    }

    // output projection: feats_paper (in buffer 0 after 2 layers) @ out_W + out_b
    gemm_kernel<false><<<gemm_grid(NP, DOUT), 256>>>(fp[0], out_W, out_b, (float*)d_out, NP, DOUT, 1.f);
}

// round 6
// speedup vs baseline: 1.3322x; 1.3322x over previous
#include <cuda_runtime.h>
#include <cuda_bf16.h>
#include <math.h>
#include <stdint.h>

// ---------------------------------------------------------------------------
// HGT forward. GEMMs via mma.sync bf16 (hi/lo 3-term = fp32-class accuracy).
// (tcgen05 is unavailable: harness builds through compute_103 base target.)
// ---------------------------------------------------------------------------
#define NA     20000
#define NP     40000
#define D      256
#define DOUT   64
#define LL     2
#define E_WB   150000
#define E_W    150000
#define E_C    300000
#define NSLOT  23   // weight slots: 2 adapt, 4 q, 6 Wk, 6 Wm, 4 aW, 1 out

// ------------------------- device scratch ----------------------------------
__device__ float g_feats_a[2][NA * D];
__device__ float g_feats_p[2][NP * D];
__device__ float g_q_a[NA * D];
__device__ float g_q_p[NP * D];
__device__ float g_khat_wb[NP * D];
__device__ float g_khat_w [NA * D];
__device__ float g_khat_c [NP * D];
__device__ float g_mhat_wb[NP * D];
__device__ float g_mhat_w [NA * D];
__device__ float g_mhat_c [NP * D];
__device__ float g_agg_a[NA * D];
__device__ float g_agg_p[NP * D];
__device__ float g_tr_a[NA * D];
__device__ float g_tr_p[NP * D];
__device__ float g_Wk[LL * 3 * D * D];
__device__ float g_bk[LL * 3 * D];
__device__ float g_Wm[LL * 3 * D * D];
__device__ float g_bm[LL * 3 * D];
// bf16 hi/lo operands
__device__ __nv_bfloat16 g_xa_hi[NA * D], g_xa_lo[NA * D];
__device__ __nv_bfloat16 g_xp_hi[NP * D], g_xp_lo[NP * D];
__device__ __nv_bfloat16 g_fa_hi[NA * D], g_fa_lo[NA * D];
__device__ __nv_bfloat16 g_fp_hi[NP * D], g_fp_lo[NP * D];
__device__ __nv_bfloat16 g_ga_hi[NA * D], g_ga_lo[NA * D];
__device__ __nv_bfloat16 g_gp_hi[NP * D], g_gp_lo[NP * D];
__device__ __nv_bfloat16 g_Whi[NSLOT * D * D], g_Wlo[NSLOT * D * D];

// ------------------------- small helpers -----------------------------------
__device__ __forceinline__ uint32_t smem_u32(const void* p) {
    uint32_t a;
    asm("{ .reg .u64 t; cvta.to.shared.u64 t, %1; cvt.u32.u64 %0, t; }" : "=r"(a) : "l"(p));
    return a;
}
#define SWZ(off) ((off) ^ (((off) >> 3) & 0x70))

#define CPASYNC16(dst, src) \
    asm volatile("cp.async.cg.shared.global [%0], [%1], 16;" :: "r"(dst), "l"(src) : "memory")

#define LDSM_X4(r0, r1, r2, r3, addr)                                         \
    asm volatile("ldmatrix.sync.aligned.m8n8.x4.shared.b16 {%0,%1,%2,%3}, [%4];" \
                 : "=r"(r0), "=r"(r1), "=r"(r2), "=r"(r3) : "r"(addr))

#define MMA16816(d, a, b0, b1)                                                \
    asm volatile("mma.sync.aligned.m16n8k16.row.col.f32.bf16.bf16.f32 "       \
                 "{%0,%1,%2,%3}, {%4,%5,%6,%7}, {%8,%9}, {%0,%1,%2,%3};"      \
                 : "+f"((d)[0]), "+f"((d)[1]), "+f"((d)[2]), "+f"((d)[3])     \
                 : "r"((a)[0]), "r"((a)[1]), "r"((a)[2]), "r"((a)[3]),        \
                   "r"(b0), "r"(b1))

__device__ __forceinline__ float gelu_exact(float x) {
    return 0.5f * x * (1.0f + erff(x * 0.70710678118654752f));
}

// ---------------------------------------------------------------------------
// combine per-head w_att/w_msg into dense K/M projection weights (fp32).
// ---------------------------------------------------------------------------
__global__ void combine_weights(const float* __restrict__ kW, const float* __restrict__ kb,
                                const float* __restrict__ mW, const float* __restrict__ mb,
                                const float* __restrict__ w_att, const float* __restrict__ w_msg,
                                float* __restrict__ Wk, float* __restrict__ bk,
                                float* __restrict__ Wm, float* __restrict__ bm)
{
    int mat = blockIdx.x;
    int l = mat / 6;
    int r6 = mat % 6;
    int e = r6 / 2;
    int which = r6 % 2;
    int d = blockIdx.y;        // 0..256 (256 == bias row)
    int j = threadIdx.x;
    int h = j >> 6;
    int jj = j & 63;
    int st = (e == 1) ? 0 : 1;

    const float* W   = which ? mW : kW;
    const float* B   = which ? mb : kb;
    const float* att = which ? w_msg : w_att;

    const float* wrow;
    if (d < 256) wrow = W + (((size_t)(l * 2 + st) * 256 + d) * 256);
    else         wrow = B + ((size_t)(l * 2 + st) * 256);
    const float* a = att + ((size_t)((l * 3 + e) * 4 + h)) * 64 * 64;

    float s = 0.f;
#pragma unroll 8
    for (int c = 0; c < 64; c++)
        s += wrow[h * 64 + c] * a[c * 64 + jj];

    float* out  = which ? Wm : Wk;
    float* outb = which ? bm : bk;
    if (d < 256) out[((size_t)(l * 3 + e) * 256 + d) * 256 + j] = s;
    else         outb[(size_t)(l * 3 + e) * 256 + j] = s;
}

// ---------------------------------------------------------------------------
// Transpose + split all weight matrices into bf16 hi/lo, K-major [n][k].
// src layouts are [K=256][Ncols]. grid (8, 8, 23), block (32, 8).
// ---------------------------------------------------------------------------
__global__ void transpose_split(const float* __restrict__ adapt_W, const float* __restrict__ qW,
                                const float* __restrict__ Wk, const float* __restrict__ Wm,
                                const float* __restrict__ aW, const float* __restrict__ outW,
                                __nv_bfloat16* __restrict__ Whi, __nv_bfloat16* __restrict__ Wlo)
{
    int slot = blockIdx.z;
    const float* src; int NC;
    if (slot < 2)       { src = adapt_W + (size_t)slot * 65536;      NC = 256; }
    else if (slot < 6)  { src = qW + (size_t)(slot - 2) * 65536;     NC = 256; }
    else if (slot < 12) { src = Wk + (size_t)(slot - 6) * 65536;     NC = 256; }
    else if (slot < 18) { src = Wm + (size_t)(slot - 12) * 65536;    NC = 256; }
    else if (slot < 22) { src = aW + (size_t)(slot - 18) * 65536;    NC = 256; }
    else                { src = outW;                                NC = 64;  }

    int k0 = blockIdx.x * 32, n0 = blockIdx.y * 32;
    if (n0 >= NC) return;
    int tx = threadIdx.x, ty = threadIdx.y;

    __shared__ float t[32][33];
#pragma unroll
    for (int i = 0; i < 4; i++) {
        int k = k0 + ty + i * 8;
        t[ty + i * 8][tx] = src[(size_t)k * NC + n0 + tx];
    }
    __syncthreads();
#pragma unroll
    for (int i = 0; i < 4; i++) {
        int n = n0 + ty + i * 8, k = k0 + tx;
        float v = t[tx][ty + i * 8];
        __nv_bfloat16 h = __float2bfloat16(v);
        float r = v - __bfloat162float(h);
        size_t o = (size_t)slot * 65536 + (size_t)n * 256 + k;
        Whi[o] = h;
        Wlo[o] = __float2bfloat16(r);
    }
}

// ---------------------------------------------------------------------------
// fp32 -> bf16 hi/lo split (vectorized).
// ---------------------------------------------------------------------------
__global__ void split_hilo(const float* __restrict__ s, __nv_bfloat16* __restrict__ hi,
                           __nv_bfloat16* __restrict__ lo, int n4)
{
    int i = blockIdx.x * blockDim.x + threadIdx.x;
    if (i >= n4) return;
    float4 v = ((const float4*)s)[i];
    __nv_bfloat16 h[4], l[4];
    float vv[4] = {v.x, v.y, v.z, v.w};
#pragma unroll
    for (int j = 0; j < 4; j++) {
        h[j] = __float2bfloat16(vv[j]);
        l[j] = __float2bfloat16(vv[j] - __bfloat162float(h[j]));
    }
    ((uint2*)hi)[i] = *(uint2*)h;
    ((uint2*)lo)[i] = *(uint2*)l;
}

// ---------------------------------------------------------------------------
// HMMA GEMM: C[M,Ntot] = epi( scale * (A @ W^T) + bias )
// A bf16 hi/lo [M][256] k-contig; W bf16 hi/lo [Ntot][256] k-contig.
// 3-term: Ahi*Whi + Ahi*Wlo + Alo*Whi, fp32 accumulation in registers.
// 256 threads = 8 warps (4M x 2N), CTA tile 128x64, warp tile 32x32,
// K chunks of 64, 2-stage cp.async pipeline, SW128-swizzled smem + ldmatrix.
// ---------------------------------------------------------------------------
#define STG_BYTES 49152   // per stage: Ahi 16K | Alo 16K | Bhi 8K | Blo 8K
#define A_HI_OFF  0
#define A_LO_OFF  16384
#define B_HI_OFF  32768
#define B_LO_OFF  40960

template <bool GELU, bool HILO>
__global__ void __launch_bounds__(256)
hmma_gemm(const __nv_bfloat16* __restrict__ Ahi, const __nv_bfloat16* __restrict__ Alo,
          const __nv_bfloat16* __restrict__ Whi, const __nv_bfloat16* __restrict__ Wlo,
          const float* __restrict__ bias, float* __restrict__ C,
          __nv_bfloat16* __restrict__ Chi, __nv_bfloat16* __restrict__ Clo,
          int M, int Ntot, float scale)
{
    extern __shared__ __align__(1024) char sm[];
    const uint32_t sb = smem_u32(sm);

    const int tid = threadIdx.x;
    const int lane = tid & 31, wid = tid >> 5;
    const int wm = wid & 3, wn = wid >> 2;          // warp grid 4 x 2
    const int m0 = blockIdx.x * 128, n0 = blockIdx.y * 64;

    // ---- chunk loader: 64-k slab of A(128 rows) and B(64 rows), hi+lo ----
    auto load_chunk = [&](int kc, int stg) {
        uint32_t base = sb + stg * STG_BYTES;
        int kb = kc * 64;
        if (tid < 128) {
            int r = tid;
            if (m0 + r < M) {
                const __nv_bfloat16* ga = Ahi + (size_t)(m0 + r) * 256 + kb;
                const __nv_bfloat16* gl = Alo + (size_t)(m0 + r) * 256 + kb;
#pragma unroll
                for (int s = 0; s < 8; s++) {
                    uint32_t o = SWZ((uint32_t)(r * 128 + s * 16));
                    CPASYNC16(base + A_HI_OFF + o, ga + s * 8);
                    CPASYNC16(base + A_LO_OFF + o, gl + s * 8);
                }
            }
        } else if (tid < 192) {
            int r = tid - 128;
            const __nv_bfloat16* gb = Whi + (size_t)(n0 + r) * 256 + kb;
            const __nv_bfloat16* gc = Wlo + (size_t)(n0 + r) * 256 + kb;
#pragma unroll
            for (int s = 0; s < 8; s++) {
                uint32_t o = SWZ((uint32_t)(r * 128 + s * 16));
                CPASYNC16(base + B_HI_OFF + o, gb + s * 8);
                CPASYNC16(base + B_LO_OFF + o, gc + s * 8);
            }
        }
        asm volatile("cp.async.commit_group;" ::: "memory");
    };

    float d[2][4][4];
#pragma unroll
    for (int i = 0; i < 2; i++)
#pragma unroll
        for (int j = 0; j < 4; j++)
#pragma unroll
            for (int r = 0; r < 4; r++) d[i][j][r] = 0.f;

    // ldmatrix per-lane address components
    const int g = lane >> 3, l7 = lane & 7;
    // A (m16k16 tile): g0: rows 0-7 k0-7 | g1: rows 8-15 k0-7 | g2: rows 0-7 k8-15 | g3: rows 8-15 k8-15
    const int a_row_off = (g & 1) ? 8 : 0;
    const int a_byte_off = (g & 2) ? 16 : 0;
    // B (n16k16 tile): g0: n0-7 k0-7 | g1: n0-7 k8-15 | g2: n8-15 k0-7 | g3: n8-15 k8-15
    const int b_row_off = (g & 2) ? 8 : 0;
    const int b_byte_off = (g & 1) ? 16 : 0;

    load_chunk(0, 0);

    for (int kc = 0; kc < 4; kc++) {
        if (kc < 3) load_chunk(kc + 1, (kc + 1) & 1);
        if (kc < 3) asm volatile("cp.async.wait_group 1;" ::: "memory");
        else        asm volatile("cp.async.wait_group 0;" ::: "memory");
        __syncthreads();

        uint32_t base = sb + (kc & 1) * STG_BYTES;
#pragma unroll
        for (int kk = 0; kk < 4; kk++) {
            int kb2 = kk * 32;
            uint32_t a_hi[2][4], a_lo[2][4], b_hi[2][4], b_lo[2][4];
#pragma unroll
            for (int i = 0; i < 2; i++) {
                uint32_t o = SWZ((uint32_t)((wm * 32 + i * 16 + l7 + a_row_off) * 128 + kb2 + a_byte_off));
                LDSM_X4(a_hi[i][0], a_hi[i][1], a_hi[i][2], a_hi[i][3], base + A_HI_OFF + o);
                LDSM_X4(a_lo[i][0], a_lo[i][1], a_lo[i][2], a_lo[i][3], base + A_LO_OFF + o);
            }
#pragma unroll
            for (int jt = 0; jt < 2; jt++) {
                uint32_t o = SWZ((uint32_t)((wn * 32 + jt * 16 + l7 + b_row_off) * 128 + kb2 + b_byte_off));
                LDSM_X4(b_hi[jt][0], b_hi[jt][1], b_hi[jt][2], b_hi[jt][3], base + B_HI_OFF + o);
                LDSM_X4(b_lo[jt][0], b_lo[jt][1], b_lo[jt][2], b_lo[jt][3], base + B_LO_OFF + o);
            }
#pragma unroll
            for (int i = 0; i < 2; i++)
#pragma unroll
                for (int j = 0; j < 4; j++) {
                    int jt = j >> 1, sel = (j & 1) * 2;
                    MMA16816(d[i][j], a_hi[i], b_hi[jt][sel], b_hi[jt][sel + 1]);
                    MMA16816(d[i][j], a_hi[i], b_lo[jt][sel], b_lo[jt][sel + 1]);
                    MMA16816(d[i][j], a_lo[i], b_hi[jt][sel], b_hi[jt][sel + 1]);
                }
        }
        __syncthreads();
    }

    // ---- epilogue ----
    const int r_base = m0 + wm * 32;
    const int c_base = n0 + wn * 32;
#pragma unroll
    for (int i = 0; i < 2; i++)
#pragma unroll
        for (int j = 0; j < 4; j++) {
            int col = c_base + j * 8 + (lane & 3) * 2;
            float2 b2 = *(const float2*)(bias + col);
#pragma unroll
            for (int half = 0; half < 2; half++) {
                int row = r_base + i * 16 + (lane >> 2) + half * 8;
                if (row >= M) continue;
                float vx = d[i][j][half * 2 + 0] * scale + b2.x;
                float vy = d[i][j][half * 2 + 1] * scale + b2.y;
                if (GELU) { vx = gelu_exact(vx); vy = gelu_exact(vy); }
                *(float2*)(C + (size_t)row * Ntot + col) = make_float2(vx, vy);
                if (HILO) {
                    union { __nv_bfloat16 b[2]; uint32_t u; } uh, ul;
                    uh.b[0] = __float2bfloat16(vx);
                    uh.b[1] = __float2bfloat16(vy);
                    ul.b[0] = __float2bfloat16(vx - __bfloat162float(uh.b[0]));
                    ul.b[1] = __float2bfloat16(vy - __bfloat162float(uh.b[1]));
                    *(uint32_t*)(Chi + (size_t)row * Ntot + col) = uh.u;
                    *(uint32_t*)(Clo + (size_t)row * Ntot + col) = ul.u;
                }
            }
        }
}

// ---------------------------------------------------------------------------
// Edge kernel: one warp per edge.
// ---------------------------------------------------------------------------
__global__ void edge_kernel(const float* __restrict__ q, const float* __restrict__ khat,
                            const float* __restrict__ mhat,
                            const int* __restrict__ src, const int* __restrict__ dst,
                            const float* __restrict__ ew, const float* __restrict__ pri,
                            float* __restrict__ agg, int E)
{
    int gw = (int)((blockIdx.x * (size_t)blockDim.x + threadIdx.x) >> 5);
    int lane = threadIdx.x & 31;
    if (gw >= E) return;

    int s = src[gw];
    int d = dst[gw];

    const float4* qr = (const float4*)(q    + (size_t)d * 256) + lane * 2;
    const float4* kr = (const float4*)(khat + (size_t)s * 256) + lane * 2;
    float4 q0 = qr[0], q1 = qr[1];
    float4 k0 = kr[0], k1 = kr[1];
    float p = q0.x * k0.x + q0.y * k0.y + q0.z * k0.z + q0.w * k0.w
            + q1.x * k1.x + q1.y * k1.y + q1.z * k1.z + q1.w * k1.w;
    p += __shfl_xor_sync(0xffffffffu, p, 1);
    p += __shfl_xor_sync(0xffffffffu, p, 2);
    p += __shfl_xor_sync(0xffffffffu, p, 4);

    int h = lane >> 3;
    float score = p * pri[h] * 0.125f;
    float attn = ew[gw] / (1.f + __expf(-score));

    const float4* mr = (const float4*)(mhat + (size_t)s * 256) + lane * 2;
    float4 m0 = mr[0], m1 = mr[1];

    float* out = agg + (size_t)d * 256 + lane * 8;
    asm volatile("red.global.add.v4.f32 [%0], {%1,%2,%3,%4};" ::
                 "l"(out), "f"(m0.x * attn), "f"(m0.y * attn),
                 "f"(m0.z * attn), "f"(m0.w * attn) : "memory");
    asm volatile("red.global.add.v4.f32 [%0], {%1,%2,%3,%4};" ::
                 "l"(out + 4), "f"(m1.x * attn), "f"(m1.y * attn),
                 "f"(m1.z * attn), "f"(m1.w * attn) : "memory");
}

// ---------------------------------------------------------------------------
// Skip-blend + LayerNorm; also emits bf16 hi/lo of the output.
// ---------------------------------------------------------------------------
__global__ void ln_blend_kernel(const float* __restrict__ tr, const float* __restrict__ feats,
                                const float* __restrict__ g, const float* __restrict__ b,
                                const float* __restrict__ skip, int skip_idx,
                                float* __restrict__ out,
                                __nv_bfloat16* __restrict__ ohi, __nv_bfloat16* __restrict__ olo,
                                int N)
{
    int row = (int)((blockIdx.x * (size_t)blockDim.x + threadIdx.x) >> 5);
    int lane = threadIdx.x & 31;
    if (row >= N) return;

    float alpha = 1.f / (1.f + __expf(-skip[skip_idx]));
    float beta = 1.f - alpha;

    const float4* t4 = (const float4*)(tr    + (size_t)row * 256) + lane * 2;
    const float4* f4 = (const float4*)(feats + (size_t)row * 256) + lane * 2;
    float4 ta = t4[0], tb = t4[1], fa = f4[0], fb = f4[1];

    float v[8];
    v[0] = ta.x * alpha + fa.x * beta;  v[1] = ta.y * alpha + fa.y * beta;
    v[2] = ta.z * alpha + fa.z * beta;  v[3] = ta.w * alpha + fa.w * beta;
    v[4] = tb.x * alpha + fb.x * beta;  v[5] = tb.y * alpha + fb.y * beta;
    v[6] = tb.z * alpha + fb.z * beta;  v[7] = tb.w * alpha + fb.w * beta;

    float s = 0.f;
#pragma unroll
    for (int i = 0; i < 8; i++) s += v[i];
#pragma unroll
    for (int o = 16; o > 0; o >>= 1) s += __shfl_xor_sync(0xffffffffu, s, o);
    float mean = s * (1.f / 256.f);

    float sq = 0.f;
#pragma unroll
    for (int i = 0; i < 8; i++) { float dv = v[i] - mean; sq += dv * dv; }
#pragma unroll
    for (int o = 16; o > 0; o >>= 1) sq += __shfl_xor_sync(0xffffffffu, sq, o);
    float rstd = rsqrtf(sq * (1.f / 256.f) + 1e-5f);

    const float4* g4 = (const float4*)(g) + lane * 2;
    const float4* b4 = (const float4*)(b) + lane * 2;
    float4 ga = g4[0], gb = g4[1], ba = b4[0], bb = b4[1];
    float gg[8] = {ga.x, ga.y, ga.z, ga.w, gb.x, gb.y, gb.z, gb.w};
    float bbv[8] = {ba.x, ba.y, ba.z, ba.w, bb.x, bb.y, bb.z, bb.w};

    float o8[8];
    union { __nv_bfloat16 b[8]; uint4 u; } uh, ul;
#pragma unroll
    for (int i = 0; i < 8; i++) {
        o8[i] = (v[i] - mean) * rstd * gg[i] + bbv[i];
        uh.b[i] = __float2bfloat16(o8[i]);
        ul.b[i] = __float2bfloat16(o8[i] - __bfloat162float(uh.b[i]));
    }

    float4* outp = (float4*)(out + (size_t)row * 256) + lane * 2;
    outp[0] = make_float4(o8[0], o8[1], o8[2], o8[3]);
    outp[1] = make_float4(o8[4], o8[5], o8[6], o8[7]);
    *(uint4*)(ohi + (size_t)row * 256 + lane * 8) = uh.u;
    *(uint4*)(olo + (size_t)row * 256 + lane * 8) = ul.u;
}

// ---------------------------------------------------------------------------
// Host orchestration.
// ---------------------------------------------------------------------------
static const int SMEM_GEMM = 2 * STG_BYTES;   // 98304

extern "C" void kernel_launch(void* const* d_in, const int* in_sizes, int n_in,
                              void* d_out, int out_size)
{
    const float* x_author = (const float*)d_in[0];
    const float* x_paper  = (const float*)d_in[1];
    const float* ew_wb    = (const float*)d_in[2];
    const float* ew_w     = (const float*)d_in[3];
    const float* ew_c     = (const float*)d_in[4];
    const float* adapt_W  = (const float*)d_in[5];
    const float* adapt_b  = (const float*)d_in[6];
    const float* kW       = (const float*)d_in[7];
    const float* kb       = (const float*)d_in[8];
    const float* qW       = (const float*)d_in[9];
    const float* qb       = (const float*)d_in[10];
    const float* mW       = (const float*)d_in[11];
    const float* mb       = (const float*)d_in[12];
    const float* aW       = (const float*)d_in[13];
    const float* ab       = (const float*)d_in[14];
    const float* w_pri    = (const float*)d_in[15];
    const float* w_att    = (const float*)d_in[16];
    const float* w_msg    = (const float*)d_in[17];
    const float* skip     = (const float*)d_in[18];
    const float* ln_g     = (const float*)d_in[19];
    const float* ln_b     = (const float*)d_in[20];
    const float* out_W    = (const float*)d_in[21];
    const float* out_b    = (const float*)d_in[22];
    const int* src_wb     = (const int*)d_in[23];
    const int* dst_wb     = (const int*)d_in[24];
    const int* src_w      = (const int*)d_in[25];
    const int* dst_w      = (const int*)d_in[26];
    const int* src_c      = (const int*)d_in[27];
    const int* dst_c      = (const int*)d_in[28];
    (void)in_sizes; (void)n_in; (void)out_size;

    cudaFuncSetAttribute(hmma_gemm<false, false>, cudaFuncAttributeMaxDynamicSharedMemorySize, SMEM_GEMM);
    cudaFuncSetAttribute(hmma_gemm<true, true>,   cudaFuncAttributeMaxDynamicSharedMemorySize, SMEM_GEMM);

    float *feats_a, *feats_p, *q_a, *q_p;
    float *khat_wb, *khat_w, *khat_c, *mhat_wb, *mhat_w, *mhat_c;
    float *agg_a, *agg_p, *tr_a, *tr_p, *Wkp, *bkp, *Wmp, *bmp;
    __nv_bfloat16 *xa_hi, *xa_lo, *xp_hi, *xp_lo, *fa_hi, *fa_lo, *fp_hi, *fp_lo;
    __nv_bfloat16 *ga_hi, *ga_lo, *gp_hi, *gp_lo, *Whi, *Wlo;
#define SYM(var, sym) cudaGetSymbolAddress((void**)&var, sym)
    SYM(feats_a, g_feats_a); SYM(feats_p, g_feats_p);
    SYM(q_a, g_q_a); SYM(q_p, g_q_p);
    SYM(khat_wb, g_khat_wb); SYM(khat_w, g_khat_w); SYM(khat_c, g_khat_c);
    SYM(mhat_wb, g_mhat_wb); SYM(mhat_w, g_mhat_w); SYM(mhat_c, g_mhat_c);
    SYM(agg_a, g_agg_a); SYM(agg_p, g_agg_p);
    SYM(tr_a, g_tr_a); SYM(tr_p, g_tr_p);
    SYM(Wkp, g_Wk); SYM(bkp, g_bk); SYM(Wmp, g_Wm); SYM(bmp, g_bm);
    SYM(xa_hi, g_xa_hi); SYM(xa_lo, g_xa_lo); SYM(xp_hi, g_xp_hi); SYM(xp_lo, g_xp_lo);
    SYM(fa_hi, g_fa_hi); SYM(fa_lo, g_fa_lo); SYM(fp_hi, g_fp_hi); SYM(fp_lo, g_fp_lo);
    SYM(ga_hi, g_ga_hi); SYM(ga_lo, g_ga_lo); SYM(gp_hi, g_gp_hi); SYM(gp_lo, g_gp_lo);
    SYM(Whi, g_Whi); SYM(Wlo, g_Wlo);
#undef SYM

    float* fa[2] = {feats_a, feats_a + (size_t)NA * D};
    float* fp[2] = {feats_p, feats_p + (size_t)NP * D};

    const int GA = (NA + 127) / 128;   // 157
    const int GP = (NP + 127) / 128;   // 313

    // 0) weight prep
    combine_weights<<<dim3(12, 257), 256>>>(kW, kb, mW, mb, w_att, w_msg, Wkp, bkp, Wmp, bmp);
    transpose_split<<<dim3(8, 8, NSLOT), dim3(32, 8)>>>(adapt_W, qW, Wkp, Wmp, aW, out_W, Whi, Wlo);

    // 1) split inputs, adapt + GELU (emits feats fp32 + hi/lo)
    split_hilo<<<(NA * D / 4 + 255) / 256, 256>>>(x_author, xa_hi, xa_lo, NA * D / 4);
    split_hilo<<<(NP * D / 4 + 255) / 256, 256>>>(x_paper, xp_hi, xp_lo, NP * D / 4);
    hmma_gemm<true, true><<<dim3(GA, 4), 256, SMEM_GEMM>>>(xa_hi, xa_lo, Whi, Wlo,
        adapt_b, fa[0], fa_hi, fa_lo, NA, 256, 1.f);
    hmma_gemm<true, true><<<dim3(GP, 4), 256, SMEM_GEMM>>>(xp_hi, xp_lo, Whi + 65536, Wlo + 65536,
        adapt_b + 256, fp[0], fp_hi, fp_lo, NP, 256, 1.f);

    for (int l = 0; l < LL; l++) {
        int cur = l & 1, nxt = 1 - cur;

#define WSLOT(s) (Whi + (size_t)(s) * 65536), (Wlo + (size_t)(s) * 65536)
        // q bases
        hmma_gemm<false, false><<<dim3(GA, 4), 256, SMEM_GEMM>>>(fa_hi, fa_lo, WSLOT(2 + l * 2 + 0),
            qb + (l * 2 + 0) * 256, q_a, nullptr, nullptr, NA, 256, 1.f);
        hmma_gemm<false, false><<<dim3(GP, 4), 256, SMEM_GEMM>>>(fp_hi, fp_lo, WSLOT(2 + l * 2 + 1),
            qb + (l * 2 + 1) * 256, q_p, nullptr, nullptr, NP, 256, 1.f);
        // khat / mhat per relation (e: CITES=0 src=paper, WRITES=1 src=author, WRITTEN_BY=2 src=paper)
        hmma_gemm<false, false><<<dim3(GP, 4), 256, SMEM_GEMM>>>(fp_hi, fp_lo, WSLOT(6 + l * 3 + 2),
            bkp + (l * 3 + 2) * 256, khat_wb, nullptr, nullptr, NP, 256, 1.f);
        hmma_gemm<false, false><<<dim3(GA, 4), 256, SMEM_GEMM>>>(fa_hi, fa_lo, WSLOT(6 + l * 3 + 1),
            bkp + (l * 3 + 1) * 256, khat_w, nullptr, nullptr, NA, 256, 1.f);
        hmma_gemm<false, false><<<dim3(GP, 4), 256, SMEM_GEMM>>>(fp_hi, fp_lo, WSLOT(6 + l * 3 + 0),
            bkp + (l * 3 + 0) * 256, khat_c, nullptr, nullptr, NP, 256, 1.f);
        hmma_gemm<false, false><<<dim3(GP, 4), 256, SMEM_GEMM>>>(fp_hi, fp_lo, WSLOT(12 + l * 3 + 2),
            bmp + (l * 3 + 2) * 256, mhat_wb, nullptr, nullptr, NP, 256, 1.f);
        hmma_gemm<false, false><<<dim3(GA, 4), 256, SMEM_GEMM>>>(fa_hi, fa_lo, WSLOT(12 + l * 3 + 1),
            bmp + (l * 3 + 1) * 256, mhat_w, nullptr, nullptr, NA, 256, 1.f);
        hmma_gemm<false, false><<<dim3(GP, 4), 256, SMEM_GEMM>>>(fp_hi, fp_lo, WSLOT(12 + l * 3 + 0),
            bmp + (l * 3 + 0) * 256, mhat_c, nullptr, nullptr, NP, 256, 1.f);

        cudaMemsetAsync(agg_a, 0, (size_t)NA * D * sizeof(float), 0);
        cudaMemsetAsync(agg_p, 0, (size_t)NP * D * sizeof(float), 0);

        edge_kernel<<<(E_WB + 7) / 8, 256>>>(q_a, khat_wb, mhat_wb, src_wb, dst_wb, ew_wb,
                                             w_pri + (l * 3 + 2) * 4, agg_a, E_WB);
        edge_kernel<<<(E_W + 7) / 8, 256>>>(q_p, khat_w, mhat_w, src_w, dst_w, ew_w,
                                            w_pri + (l * 3 + 1) * 4, agg_p, E_W);
        edge_kernel<<<(E_C + 7) / 8, 256>>>(q_p, khat_c, mhat_c, src_c, dst_c, ew_c,
                                            w_pri + (l * 3 + 0) * 4, agg_p, E_C);

        // agg -> hi/lo, then a-projection (0.5 cross-relation mean via scale)
        split_hilo<<<(NA * D / 4 + 255) / 256, 256>>>(agg_a, ga_hi, ga_lo, NA * D / 4);
        split_hilo<<<(NP * D / 4 + 255) / 256, 256>>>(agg_p, gp_hi, gp_lo, NP * D / 4);
        hmma_gemm<false, false><<<dim3(GA, 4), 256, SMEM_GEMM>>>(ga_hi, ga_lo, WSLOT(18 + l * 2 + 0),
            ab + (l * 2 + 0) * 256, tr_a, nullptr, nullptr, NA, 256, 1.0f);
        hmma_gemm<false, false><<<dim3(GP, 4), 256, SMEM_GEMM>>>(gp_hi, gp_lo, WSLOT(18 + l * 2 + 1),
            ab + (l * 2 + 1) * 256, tr_p, nullptr, nullptr, NP, 256, 0.5f);
#undef WSLOT

        // skip blend + LN (emits fp32 feats + hi/lo for next layer / out proj)
        ln_blend_kernel<<<(NA + 7) / 8, 256>>>(tr_a, fa[cur], ln_g + (l * 2 + 0) * 256,
            ln_b + (l * 2 + 0) * 256, skip, l * 3 + 0, fa[nxt], fa_hi, fa_lo, NA);
        ln_blend_kernel<<<(NP + 7) / 8, 256>>>(tr_p, fp[cur], ln_g + (l * 2 + 1) * 256,
            ln_b + (l * 2 + 1) * 256, skip, l * 3 + 1, fp[nxt], fp_hi, fp_lo, NP);
    }

    // output projection: paper feats (hi/lo from last LN) @ out_W + out_b
    hmma_gemm<false, false><<<dim3(GP, 1), 256, SMEM_GEMM>>>(fp_hi, fp_lo,
        Whi + (size_t)22 * 65536, Wlo + (size_t)22 * 65536,
        out_b, (float*)d_out, nullptr, nullptr, NP, 64, 1.f);
}

// round 7
// speedup vs baseline: 1.4234x; 1.0685x over previous
#include <cuda_runtime.h>
#include <cuda_bf16.h>
#include <math.h>
#include <stdint.h>

// ---------------------------------------------------------------------------
// HGT forward. GEMMs via mma.sync bf16 (hi/lo 3-term = fp32-class accuracy).
// R7: batched per-layer projections (strided outputs) + 128x128 CTA tile.
// ---------------------------------------------------------------------------
#define NA     20000
#define NP     40000
#define D      256
#define DOUT   64
#define LL     2
#define E_WB   150000
#define E_W    150000
#define E_C    300000
#define NSLOT  23
// paper proj row: [0,256)=q | [256,512)=k_wb | [512,768)=k_c | [768,1024)=m_wb | [1024,1280)=m_c
#define PSTR   1280
// author proj row: [0,256)=q | [256,512)=k_w | [512,768)=m_w
#define ASTR   768

// ------------------------- device scratch ----------------------------------
__device__ float g_feats_a[2][NA * D];
__device__ float g_feats_p[2][NP * D];
__device__ float g_proj_a[NA * ASTR];
__device__ float g_proj_p[NP * PSTR];
__device__ float g_agg_a[NA * D];
__device__ float g_agg_p[NP * D];
__device__ float g_tr_a[NA * D];
__device__ float g_tr_p[NP * D];
__device__ float g_Wk[LL * 3 * D * D];
__device__ float g_bk[LL * 3 * D];
__device__ float g_Wm[LL * 3 * D * D];
__device__ float g_bm[LL * 3 * D];
__device__ float g_bias_p[LL * PSTR];
__device__ float g_bias_a[LL * ASTR];
// bf16 hi/lo operands
__device__ __nv_bfloat16 g_xa_hi[NA * D], g_xa_lo[NA * D];
__device__ __nv_bfloat16 g_xp_hi[NP * D], g_xp_lo[NP * D];
__device__ __nv_bfloat16 g_fa_hi[NA * D], g_fa_lo[NA * D];
__device__ __nv_bfloat16 g_fp_hi[NP * D], g_fp_lo[NP * D];
__device__ __nv_bfloat16 g_ga_hi[NA * D], g_ga_lo[NA * D];
__device__ __nv_bfloat16 g_gp_hi[NP * D], g_gp_lo[NP * D];
__device__ __nv_bfloat16 g_Whi[NSLOT * D * D], g_Wlo[NSLOT * D * D];

// ------------------------- small helpers -----------------------------------
__device__ __forceinline__ uint32_t smem_u32(const void* p) {
    uint32_t a;
    asm("{ .reg .u64 t; cvta.to.shared.u64 t, %1; cvt.u32.u64 %0, t; }" : "=r"(a) : "l"(p));
    return a;
}
#define SWZ(off) ((off) ^ (((off) >> 3) & 0x70))

#define CPASYNC16(dst, src) \
    asm volatile("cp.async.cg.shared.global [%0], [%1], 16;" :: "r"(dst), "l"(src) : "memory")

#define LDSM_X4(r0, r1, r2, r3, addr)                                         \
    asm volatile("ldmatrix.sync.aligned.m8n8.x4.shared.b16 {%0,%1,%2,%3}, [%4];" \
                 : "=r"(r0), "=r"(r1), "=r"(r2), "=r"(r3) : "r"(addr))

#define MMA16816(d, a, b0, b1)                                                \
    asm volatile("mma.sync.aligned.m16n8k16.row.col.f32.bf16.bf16.f32 "       \
                 "{%0,%1,%2,%3}, {%4,%5,%6,%7}, {%8,%9}, {%0,%1,%2,%3};"      \
                 : "+f"((d)[0]), "+f"((d)[1]), "+f"((d)[2]), "+f"((d)[3])     \
                 : "r"((a)[0]), "r"((a)[1]), "r"((a)[2]), "r"((a)[3]),        \
                   "r"(b0), "r"(b1))

__device__ __forceinline__ float gelu_exact(float x) {
    return 0.5f * x * (1.0f + erff(x * 0.70710678118654752f));
}

// ---------------------------------------------------------------------------
// combine per-head w_att/w_msg into dense K/M projection weights (fp32).
// ---------------------------------------------------------------------------
__global__ void combine_weights(const float* __restrict__ kW, const float* __restrict__ kb,
                                const float* __restrict__ mW, const float* __restrict__ mb,
                                const float* __restrict__ w_att, const float* __restrict__ w_msg,
                                float* __restrict__ Wk, float* __restrict__ bk,
                                float* __restrict__ Wm, float* __restrict__ bm)
{
    int mat = blockIdx.x;
    int l = mat / 6;
    int r6 = mat % 6;
    int e = r6 / 2;
    int which = r6 % 2;
    int d = blockIdx.y;        // 0..256 (256 == bias row)
    int j = threadIdx.x;
    int h = j >> 6;
    int jj = j & 63;
    int st = (e == 1) ? 0 : 1;

    const float* W   = which ? mW : kW;
    const float* B   = which ? mb : kb;
    const float* att = which ? w_msg : w_att;

    const float* wrow;
    if (d < 256) wrow = W + (((size_t)(l * 2 + st) * 256 + d) * 256);
    else         wrow = B + ((size_t)(l * 2 + st) * 256);
    const float* a = att + ((size_t)((l * 3 + e) * 4 + h)) * 64 * 64;

    float s = 0.f;
#pragma unroll 8
    for (int c = 0; c < 64; c++)
        s += wrow[h * 64 + c] * a[c * 64 + jj];

    float* out  = which ? Wm : Wk;
    float* outb = which ? bm : bk;
    if (d < 256) out[((size_t)(l * 3 + e) * 256 + d) * 256 + j] = s;
    else         outb[(size_t)(l * 3 + e) * 256 + j] = s;
}

// ---------------------------------------------------------------------------
// Transpose + split all weight matrices into bf16 hi/lo, K-major [n][k].
// Slot order (for batched projections):
//   0,1: adapt a/p
//   2+l*8+{0..7}: q_p, k_wb, k_c, m_wb, m_c, q_a, k_w, m_w   (layer l)
//   18+l*2+nt: aW
//   22: out_W
// ---------------------------------------------------------------------------
__global__ void transpose_split(const float* __restrict__ adapt_W, const float* __restrict__ qW,
                                const float* __restrict__ Wk, const float* __restrict__ Wm,
                                const float* __restrict__ aW, const float* __restrict__ outW,
                                __nv_bfloat16* __restrict__ Whi, __nv_bfloat16* __restrict__ Wlo)
{
    int slot = blockIdx.z;
    const float* src; int NC = 256;
    if (slot < 2)        src = adapt_W + (size_t)slot * 65536;
    else if (slot < 18) {
        int l = (slot - 2) / 8, o = (slot - 2) % 8;
        switch (o) {
            case 0: src = qW + (size_t)(l * 2 + 1) * 65536; break;
            case 1: src = Wk + (size_t)(l * 3 + 2) * 65536; break;
            case 2: src = Wk + (size_t)(l * 3 + 0) * 65536; break;
            case 3: src = Wm + (size_t)(l * 3 + 2) * 65536; break;
            case 4: src = Wm + (size_t)(l * 3 + 0) * 65536; break;
            case 5: src = qW + (size_t)(l * 2 + 0) * 65536; break;
            case 6: src = Wk + (size_t)(l * 3 + 1) * 65536; break;
            default: src = Wm + (size_t)(l * 3 + 1) * 65536; break;
        }
    }
    else if (slot < 22)  src = aW + (size_t)(slot - 18) * 65536;
    else               { src = outW; NC = 64; }

    int k0 = blockIdx.x * 32, n0 = blockIdx.y * 32;
    if (n0 >= NC) return;
    int tx = threadIdx.x, ty = threadIdx.y;

    __shared__ float t[32][33];
#pragma unroll
    for (int i = 0; i < 4; i++) {
        int k = k0 + ty + i * 8;
        t[ty + i * 8][tx] = src[(size_t)k * NC + n0 + tx];
    }
    __syncthreads();
#pragma unroll
    for (int i = 0; i < 4; i++) {
        int n = n0 + ty + i * 8, k = k0 + tx;
        float v = t[tx][ty + i * 8];
        __nv_bfloat16 h = __float2bfloat16(v);
        float r = v - __bfloat162float(h);
        size_t o = (size_t)slot * 65536 + (size_t)n * 256 + k;
        Whi[o] = h;
        Wlo[o] = __float2bfloat16(r);
    }
}

// ---------------------------------------------------------------------------
// Pack per-layer projection biases into the batched column layout.
// ---------------------------------------------------------------------------
__global__ void pack_bias(const float* __restrict__ qb, const float* __restrict__ bk,
                          const float* __restrict__ bm,
                          float* __restrict__ bp, float* __restrict__ ba)
{
    int idx = blockIdx.x * 256 + threadIdx.x;    // 2 * 2048
    if (idx >= LL * 2048) return;
    int l = idx / 2048, r = idx % 2048;
    int seg = r >> 8, c = r & 255;
    float v;
    switch (seg) {
        case 0: v = qb[(l * 2 + 1) * 256 + c]; break;
        case 1: v = bk[(l * 3 + 2) * 256 + c]; break;
        case 2: v = bk[(l * 3 + 0) * 256 + c]; break;
        case 3: v = bm[(l * 3 + 2) * 256 + c]; break;
        case 4: v = bm[(l * 3 + 0) * 256 + c]; break;
        case 5: v = qb[(l * 2 + 0) * 256 + c]; break;
        case 6: v = bk[(l * 3 + 1) * 256 + c]; break;
        default: v = bm[(l * 3 + 1) * 256 + c]; break;
    }
    if (seg < 5) bp[l * PSTR + seg * 256 + c] = v;
    else         ba[l * ASTR + (seg - 5) * 256 + c] = v;
}

// ---------------------------------------------------------------------------
// fp32 -> bf16 hi/lo split (vectorized).
// ---------------------------------------------------------------------------
__global__ void split_hilo(const float* __restrict__ s, __nv_bfloat16* __restrict__ hi,
                           __nv_bfloat16* __restrict__ lo, int n4)
{
    int i = blockIdx.x * blockDim.x + threadIdx.x;
    if (i >= n4) return;
    float4 v = ((const float4*)s)[i];
    __nv_bfloat16 h[4], l[4];
    float vv[4] = {v.x, v.y, v.z, v.w};
#pragma unroll
    for (int j = 0; j < 4; j++) {
        h[j] = __float2bfloat16(vv[j]);
        l[j] = __float2bfloat16(vv[j] - __bfloat162float(h[j]));
    }
    ((uint2*)hi)[i] = *(uint2*)h;
    ((uint2*)lo)[i] = *(uint2*)l;
}

// ---------------------------------------------------------------------------
// HMMA GEMM: C[M, grid.y*BN] (row stride Ntot) = epi( scale*(A @ W^T) + bias )
// A bf16 hi/lo [M][256] k-contig; W bf16 hi/lo [rows][256] k-contig.
// 3-term: Ahi*Whi + Ahi*Wlo + Alo*Whi, fp32 register accumulation.
// 256 threads = 8 warps (4M x 2N), CTA tile 128 x BN, warp tile 32 x BN/2,
// K chunks of 64, 2-stage cp.async pipeline, SW128 swizzle + ldmatrix.
// ---------------------------------------------------------------------------
#define A_HI_OFF  0
#define A_LO_OFF  16384

template <int BN, bool GELU, bool HILO>
__global__ void __launch_bounds__(256)
hmma_gemm(const __nv_bfloat16* __restrict__ Ahi, const __nv_bfloat16* __restrict__ Alo,
          const __nv_bfloat16* __restrict__ Whi, const __nv_bfloat16* __restrict__ Wlo,
          const float* __restrict__ bias, float* __restrict__ C,
          __nv_bfloat16* __restrict__ Chi, __nv_bfloat16* __restrict__ Clo,
          int M, int Ntot, float scale)
{
    constexpr int WN = BN / 2;          // warp n extent
    constexpr int NT = WN / 16;         // n16 tiles per warp
    constexpr int B_HI_OFF = 32768;
    constexpr int B_LO_OFF = 32768 + BN * 128;
    constexpr int STG = 32768 + 2 * BN * 128;

    extern __shared__ __align__(1024) char sm[];
    const uint32_t sb = smem_u32(sm);

    const int tid = threadIdx.x;
    const int lane = tid & 31, wid = tid >> 5;
    const int wm = wid & 3, wn = wid >> 2;          // warp grid 4 x 2
    const int m0 = blockIdx.x * 128, n0 = blockIdx.y * BN;

    auto load_chunk = [&](int kc, int stg) {
        uint32_t base = sb + stg * STG;
        int kb = kc * 64;
        if (tid < 128) {
            int r = tid;
            if (m0 + r < M) {
                const __nv_bfloat16* ga = Ahi + (size_t)(m0 + r) * 256 + kb;
                const __nv_bfloat16* gl = Alo + (size_t)(m0 + r) * 256 + kb;
#pragma unroll
                for (int s = 0; s < 8; s++) {
                    uint32_t o = SWZ((uint32_t)(r * 128 + s * 16));
                    CPASYNC16(base + A_HI_OFF + o, ga + s * 8);
                    CPASYNC16(base + A_LO_OFF + o, gl + s * 8);
                }
            }
        } else if (tid < 128 + BN) {
            int r = tid - 128;
            const __nv_bfloat16* gb = Whi + (size_t)(n0 + r) * 256 + kb;
            const __nv_bfloat16* gc = Wlo + (size_t)(n0 + r) * 256 + kb;
#pragma unroll
            for (int s = 0; s < 8; s++) {
                uint32_t o = SWZ((uint32_t)(r * 128 + s * 16));
                CPASYNC16(base + B_HI_OFF + o, gb + s * 8);
                CPASYNC16(base + B_LO_OFF + o, gc + s * 8);
            }
        }
        asm volatile("cp.async.commit_group;" ::: "memory");
    };

    float d[2][2 * NT][4];
#pragma unroll
    for (int i = 0; i < 2; i++)
#pragma unroll
        for (int j = 0; j < 2 * NT; j++)
#pragma unroll
            for (int r = 0; r < 4; r++) d[i][j][r] = 0.f;

    const int g = lane >> 3, l7 = lane & 7;
    const int a_row_off = (g & 1) ? 8 : 0;
    const int a_byte_off = (g & 2) ? 16 : 0;
    const int b_row_off = (g & 2) ? 8 : 0;
    const int b_byte_off = (g & 1) ? 16 : 0;

    load_chunk(0, 0);

    for (int kc = 0; kc < 4; kc++) {
        if (kc < 3) load_chunk(kc + 1, (kc + 1) & 1);
        if (kc < 3) asm volatile("cp.async.wait_group 1;" ::: "memory");
        else        asm volatile("cp.async.wait_group 0;" ::: "memory");
        __syncthreads();

        uint32_t base = sb + (kc & 1) * STG;
#pragma unroll
        for (int kk = 0; kk < 4; kk++) {
            int kb2 = kk * 32;
            uint32_t a_hi[2][4], a_lo[2][4], b_hi[NT][4], b_lo[NT][4];
#pragma unroll
            for (int i = 0; i < 2; i++) {
                uint32_t o = SWZ((uint32_t)((wm * 32 + i * 16 + l7 + a_row_off) * 128 + kb2 + a_byte_off));
                LDSM_X4(a_hi[i][0], a_hi[i][1], a_hi[i][2], a_hi[i][3], base + A_HI_OFF + o);
                LDSM_X4(a_lo[i][0], a_lo[i][1], a_lo[i][2], a_lo[i][3], base + A_LO_OFF + o);
            }
#pragma unroll
            for (int jt = 0; jt < NT; jt++) {
                uint32_t o = SWZ((uint32_t)((wn * WN + jt * 16 + l7 + b_row_off) * 128 + kb2 + b_byte_off));
                LDSM_X4(b_hi[jt][0], b_hi[jt][1], b_hi[jt][2], b_hi[jt][3], base + B_HI_OFF + o);
                LDSM_X4(b_lo[jt][0], b_lo[jt][1], b_lo[jt][2], b_lo[jt][3], base + B_LO_OFF + o);
            }
#pragma unroll
            for (int i = 0; i < 2; i++)
#pragma unroll
                for (int jt = 0; jt < NT; jt++)
#pragma unroll
                    for (int half = 0; half < 2; half++) {
                        int j = jt * 2 + half, sel = half * 2;
                        MMA16816(d[i][j], a_hi[i], b_hi[jt][sel], b_hi[jt][sel + 1]);
                        MMA16816(d[i][j], a_hi[i], b_lo[jt][sel], b_lo[jt][sel + 1]);
                        MMA16816(d[i][j], a_lo[i], b_hi[jt][sel], b_hi[jt][sel + 1]);
                    }
        }
        __syncthreads();
    }

    // ---- epilogue ----
    const int r_base = m0 + wm * 32;
    const int c_base = n0 + wn * WN;
#pragma unroll
    for (int i = 0; i < 2; i++)
#pragma unroll
        for (int j = 0; j < 2 * NT; j++) {
            int col = c_base + j * 8 + (lane & 3) * 2;
            float2 b2 = *(const float2*)(bias + col);
#pragma unroll
            for (int half = 0; half < 2; half++) {
                int row = r_base + i * 16 + (lane >> 2) + half * 8;
                if (row >= M) continue;
                float vx = d[i][j][half * 2 + 0] * scale + b2.x;
                float vy = d[i][j][half * 2 + 1] * scale + b2.y;
                if (GELU) { vx = gelu_exact(vx); vy = gelu_exact(vy); }
                *(float2*)(C + (size_t)row * Ntot + col) = make_float2(vx, vy);
                if (HILO) {
                    union { __nv_bfloat16 b[2]; uint32_t u; } uh, ul;
                    uh.b[0] = __float2bfloat16(vx);
                    uh.b[1] = __float2bfloat16(vy);
                    ul.b[0] = __float2bfloat16(vx - __bfloat162float(uh.b[0]));
                    ul.b[1] = __float2bfloat16(vy - __bfloat162float(uh.b[1]));
                    *(uint32_t*)(Chi + (size_t)row * Ntot + col) = uh.u;
                    *(uint32_t*)(Clo + (size_t)row * Ntot + col) = ul.u;
                }
            }
        }
}

// ---------------------------------------------------------------------------
// Edge kernel: one warp per edge; q/k/m read from strided projection buffers.
// ---------------------------------------------------------------------------
__global__ void edge_kernel(const float* __restrict__ q, int qs,
                            const float* __restrict__ khat, const float* __restrict__ mhat, int kms,
                            const int* __restrict__ src, const int* __restrict__ dst,
                            const float* __restrict__ ew, const float* __restrict__ pri,
                            float* __restrict__ agg, int E)
{
    int gw = (int)((blockIdx.x * (size_t)blockDim.x + threadIdx.x) >> 5);
    int lane = threadIdx.x & 31;
    if (gw >= E) return;

    int s = src[gw];
    int d = dst[gw];

    const float4* qr = (const float4*)(q    + (size_t)d * qs) + lane * 2;
    const float4* kr = (const float4*)(khat + (size_t)s * kms) + lane * 2;
    float4 q0 = qr[0], q1 = qr[1];
    float4 k0 = kr[0], k1 = kr[1];
    float p = q0.x * k0.x + q0.y * k0.y + q0.z * k0.z + q0.w * k0.w
            + q1.x * k1.x + q1.y * k1.y + q1.z * k1.z + q1.w * k1.w;
    p += __shfl_xor_sync(0xffffffffu, p, 1);
    p += __shfl_xor_sync(0xffffffffu, p, 2);
    p += __shfl_xor_sync(0xffffffffu, p, 4);

    int h = lane >> 3;
    float score = p * pri[h] * 0.125f;
    float attn = ew[gw] / (1.f + __expf(-score));

    const float4* mr = (const float4*)(mhat + (size_t)s * kms) + lane * 2;
    float4 m0 = mr[0], m1 = mr[1];

    float* out = agg + (size_t)d * 256 + lane * 8;
    asm volatile("red.global.add.v4.f32 [%0], {%1,%2,%3,%4};" ::
                 "l"(out), "f"(m0.x * attn), "f"(m0.y * attn),
                 "f"(m0.z * attn), "f"(m0.w * attn) : "memory");
    asm volatile("red.global.add.v4.f32 [%0], {%1,%2,%3,%4};" ::
                 "l"(out + 4), "f"(m1.x * attn), "f"(m1.y * attn),
                 "f"(m1.z * attn), "f"(m1.w * attn) : "memory");
}

// ---------------------------------------------------------------------------
// Skip-blend + LayerNorm; also emits bf16 hi/lo of the output.
// ---------------------------------------------------------------------------
__global__ void ln_blend_kernel(const float* __restrict__ tr, const float* __restrict__ feats,
                                const float* __restrict__ g, const float* __restrict__ b,
                                const float* __restrict__ skip, int skip_idx,
                                float* __restrict__ out,
                                __nv_bfloat16* __restrict__ ohi, __nv_bfloat16* __restrict__ olo,
                                int N)
{
    int row = (int)((blockIdx.x * (size_t)blockDim.x + threadIdx.x) >> 5);
    int lane = threadIdx.x & 31;
    if (row >= N) return;

    float alpha = 1.f / (1.f + __expf(-skip[skip_idx]));
    float beta = 1.f - alpha;

    const float4* t4 = (const float4*)(tr    + (size_t)row * 256) + lane * 2;
    const float4* f4 = (const float4*)(feats + (size_t)row * 256) + lane * 2;
    float4 ta = t4[0], tb = t4[1], fa = f4[0], fb = f4[1];

    float v[8];
    v[0] = ta.x * alpha + fa.x * beta;  v[1] = ta.y * alpha + fa.y * beta;
    v[2] = ta.z * alpha + fa.z * beta;  v[3] = ta.w * alpha + fa.w * beta;
    v[4] = tb.x * alpha + fb.x * beta;  v[5] = tb.y * alpha + fb.y * beta;
    v[6] = tb.z * alpha + fb.z * beta;  v[7] = tb.w * alpha + fb.w * beta;

    float s = 0.f;
#pragma unroll
    for (int i = 0; i < 8; i++) s += v[i];
#pragma unroll
    for (int o = 16; o > 0; o >>= 1) s += __shfl_xor_sync(0xffffffffu, s, o);
    float mean = s * (1.f / 256.f);

    float sq = 0.f;
#pragma unroll
    for (int i = 0; i < 8; i++) { float dv = v[i] - mean; sq += dv * dv; }
#pragma unroll
    for (int o = 16; o > 0; o >>= 1) sq += __shfl_xor_sync(0xffffffffu, sq, o);
    float rstd = rsqrtf(sq * (1.f / 256.f) + 1e-5f);

    const float4* g4 = (const float4*)(g) + lane * 2;
    const float4* b4 = (const float4*)(b) + lane * 2;
    float4 ga = g4[0], gb = g4[1], ba = b4[0], bb = b4[1];
    float gg[8] = {ga.x, ga.y, ga.z, ga.w, gb.x, gb.y, gb.z, gb.w};
    float bbv[8] = {ba.x, ba.y, ba.z, ba.w, bb.x, bb.y, bb.z, bb.w};

    float o8[8];
    union { __nv_bfloat16 b[8]; uint4 u; } uh, ul;
#pragma unroll
    for (int i = 0; i < 8; i++) {
        o8[i] = (v[i] - mean) * rstd * gg[i] + bbv[i];
        uh.b[i] = __float2bfloat16(o8[i]);
        ul.b[i] = __float2bfloat16(o8[i] - __bfloat162float(uh.b[i]));
    }

    float4* outp = (float4*)(out + (size_t)row * 256) + lane * 2;
    outp[0] = make_float4(o8[0], o8[1], o8[2], o8[3]);
    outp[1] = make_float4(o8[4], o8[5], o8[6], o8[7]);
    *(uint4*)(ohi + (size_t)row * 256 + lane * 8) = uh.u;
    *(uint4*)(olo + (size_t)row * 256 + lane * 8) = ul.u;
}

// ---------------------------------------------------------------------------
// Host orchestration.
// ---------------------------------------------------------------------------
static const int SMEM128 = 2 * (32768 + 2 * 128 * 128);   // 131072
static const int SMEM64  = 2 * (32768 + 2 * 64 * 128);    // 98304

extern "C" void kernel_launch(void* const* d_in, const int* in_sizes, int n_in,
                              void* d_out, int out_size)
{
    const float* x_author = (const float*)d_in[0];
    const float* x_paper  = (const float*)d_in[1];
    const float* ew_wb    = (const float*)d_in[2];
    const float* ew_w     = (const float*)d_in[3];
    const float* ew_c     = (const float*)d_in[4];
    const float* adapt_W  = (const float*)d_in[5];
    const float* adapt_b  = (const float*)d_in[6];
    const float* kW       = (const float*)d_in[7];
    const float* kb       = (const float*)d_in[8];
    const float* qW       = (const float*)d_in[9];
    const float* qb       = (const float*)d_in[10];
    const float* mW       = (const float*)d_in[11];
    const float* mb       = (const float*)d_in[12];
    const float* aW       = (const float*)d_in[13];
    const float* ab       = (const float*)d_in[14];
    const float* w_pri    = (const float*)d_in[15];
    const float* w_att    = (const float*)d_in[16];
    const float* w_msg    = (const float*)d_in[17];
    const float* skip     = (const float*)d_in[18];
    const float* ln_g     = (const float*)d_in[19];
    const float* ln_b     = (const float*)d_in[20];
    const float* out_W    = (const float*)d_in[21];
    const float* out_b    = (const float*)d_in[22];
    const int* src_wb     = (const int*)d_in[23];
    const int* dst_wb     = (const int*)d_in[24];
    const int* src_w      = (const int*)d_in[25];
    const int* dst_w      = (const int*)d_in[26];
    const int* src_c      = (const int*)d_in[27];
    const int* dst_c      = (const int*)d_in[28];
    (void)in_sizes; (void)n_in; (void)out_size;

    cudaFuncSetAttribute(hmma_gemm<128, false, false>, cudaFuncAttributeMaxDynamicSharedMemorySize, SMEM128);
    cudaFuncSetAttribute(hmma_gemm<128, true, true>,   cudaFuncAttributeMaxDynamicSharedMemorySize, SMEM128);
    cudaFuncSetAttribute(hmma_gemm<64, false, false>,  cudaFuncAttributeMaxDynamicSharedMemorySize, SMEM64);

    float *feats_a, *feats_p, *proj_a, *proj_p;
    float *agg_a, *agg_p, *tr_a, *tr_p, *Wkp, *bkp, *Wmp, *bmp, *bias_p, *bias_a;
    __nv_bfloat16 *xa_hi, *xa_lo, *xp_hi, *xp_lo, *fa_hi, *fa_lo, *fp_hi, *fp_lo;
    __nv_bfloat16 *ga_hi, *ga_lo, *gp_hi, *gp_lo, *Whi, *Wlo;
#define SYM(var, sym) cudaGetSymbolAddress((void**)&var, sym)
    SYM(feats_a, g_feats_a); SYM(feats_p, g_feats_p);
    SYM(proj_a, g_proj_a); SYM(proj_p, g_proj_p);
    SYM(agg_a, g_agg_a); SYM(agg_p, g_agg_p);
    SYM(tr_a, g_tr_a); SYM(tr_p, g_tr_p);
    SYM(Wkp, g_Wk); SYM(bkp, g_bk); SYM(Wmp, g_Wm); SYM(bmp, g_bm);
    SYM(bias_p, g_bias_p); SYM(bias_a, g_bias_a);
    SYM(xa_hi, g_xa_hi); SYM(xa_lo, g_xa_lo); SYM(xp_hi, g_xp_hi); SYM(xp_lo, g_xp_lo);
    SYM(fa_hi, g_fa_hi); SYM(fa_lo, g_fa_lo); SYM(fp_hi, g_fp_hi); SYM(fp_lo, g_fp_lo);
    SYM(ga_hi, g_ga_hi); SYM(ga_lo, g_ga_lo); SYM(gp_hi, g_gp_hi); SYM(gp_lo, g_gp_lo);
    SYM(Whi, g_Whi); SYM(Wlo, g_Wlo);
#undef SYM

    float* fa[2] = {feats_a, feats_a + (size_t)NA * D};
    float* fp[2] = {feats_p, feats_p + (size_t)NP * D};

    const int GA = (NA + 127) / 128;   // 157
    const int GP = (NP + 127) / 128;   // 313

    // 0) weight prep
    combine_weights<<<dim3(12, 257), 256>>>(kW, kb, mW, mb, w_att, w_msg, Wkp, bkp, Wmp, bmp);
    transpose_split<<<dim3(8, 8, NSLOT), dim3(32, 8)>>>(adapt_W, qW, Wkp, Wmp, aW, out_W, Whi, Wlo);
    pack_bias<<<(LL * 2048 + 255) / 256, 256>>>(qb, bkp, bmp, bias_p, bias_a);

    // 1) split inputs, adapt + GELU (emits feats fp32 + hi/lo)
    split_hilo<<<(NA * D / 4 + 255) / 256, 256>>>(x_author, xa_hi, xa_lo, NA * D / 4);
    split_hilo<<<(NP * D / 4 + 255) / 256, 256>>>(x_paper, xp_hi, xp_lo, NP * D / 4);
    hmma_gemm<128, true, true><<<dim3(GA, 2), 256, SMEM128>>>(xa_hi, xa_lo, Whi, Wlo,
        adapt_b, fa[0], fa_hi, fa_lo, NA, 256, 1.f);
    hmma_gemm<128, true, true><<<dim3(GP, 2), 256, SMEM128>>>(xp_hi, xp_lo, Whi + 65536, Wlo + 65536,
        adapt_b + 256, fp[0], fp_hi, fp_lo, NP, 256, 1.f);

    for (int l = 0; l < LL; l++) {
        int cur = l & 1, nxt = 1 - cur;

        // batched projections: paper 5 mats (q, k_wb, k_c, m_wb, m_c), author 3 (q, k_w, m_w)
        const size_t psl = (size_t)(2 + l * 8) * 65536;
        const size_t asl = (size_t)(2 + l * 8 + 5) * 65536;
        hmma_gemm<128, false, false><<<dim3(GP, PSTR / 128), 256, SMEM128>>>(fp_hi, fp_lo,
            Whi + psl, Wlo + psl, bias_p + l * PSTR, proj_p, nullptr, nullptr, NP, PSTR, 1.f);
        hmma_gemm<128, false, false><<<dim3(GA, ASTR / 128), 256, SMEM128>>>(fa_hi, fa_lo,
            Whi + asl, Wlo + asl, bias_a + l * ASTR, proj_a, nullptr, nullptr, NA, ASTR, 1.f);

        cudaMemsetAsync(agg_a, 0, (size_t)NA * D * sizeof(float), 0);
        cudaMemsetAsync(agg_p, 0, (size_t)NP * D * sizeof(float), 0);

        // WRITTEN_BY: dst author (q in proj_a), src paper (k/m in proj_p)
        edge_kernel<<<(E_WB + 7) / 8, 256>>>(proj_a, ASTR, proj_p + 256, proj_p + 768, PSTR,
            src_wb, dst_wb, ew_wb, w_pri + (l * 3 + 2) * 4, agg_a, E_WB);
        // WRITES: dst paper, src author
        edge_kernel<<<(E_W + 7) / 8, 256>>>(proj_p, PSTR, proj_a + 256, proj_a + 512, ASTR,
            src_w, dst_w, ew_w, w_pri + (l * 3 + 1) * 4, agg_p, E_W);
        // CITES: dst paper, src paper
        edge_kernel<<<(E_C + 7) / 8, 256>>>(proj_p, PSTR, proj_p + 512, proj_p + 1024, PSTR,
            src_c, dst_c, ew_c, w_pri + (l * 3 + 0) * 4, agg_p, E_C);

        // agg -> hi/lo, then a-projection (0.5 cross-relation mean via scale)
        split_hilo<<<(NA * D / 4 + 255) / 256, 256>>>(agg_a, ga_hi, ga_lo, NA * D / 4);
        split_hilo<<<(NP * D / 4 + 255) / 256, 256>>>(agg_p, gp_hi, gp_lo, NP * D / 4);
        const size_t aa = (size_t)(18 + l * 2 + 0) * 65536;
        const size_t ap = (size_t)(18 + l * 2 + 1) * 65536;
        hmma_gemm<128, false, false><<<dim3(GA, 2), 256, SMEM128>>>(ga_hi, ga_lo,
            Whi + aa, Wlo + aa, ab + (l * 2 + 0) * 256, tr_a, nullptr, nullptr, NA, 256, 1.0f);
        hmma_gemm<128, false, false><<<dim3(GP, 2), 256, SMEM128>>>(gp_hi, gp_lo,
            Whi + ap, Wlo + ap, ab + (l * 2 + 1) * 256, tr_p, nullptr, nullptr, NP, 256, 0.5f);

        // skip blend + LN (emits fp32 feats + hi/lo for next layer / out proj)
        ln_blend_kernel<<<(NA + 7) / 8, 256>>>(tr_a, fa[cur], ln_g + (l * 2 + 0) * 256,
            ln_b + (l * 2 + 0) * 256, skip, l * 3 + 0, fa[nxt], fa_hi, fa_lo, NA);
        ln_blend_kernel<<<(NP + 7) / 8, 256>>>(tr_p, fp[cur], ln_g + (l * 2 + 1) * 256,
            ln_b + (l * 2 + 1) * 256, skip, l * 3 + 1, fp[nxt], fp_hi, fp_lo, NP);
    }

    // output projection: paper feats (hi/lo from last LN) @ out_W + out_b
    hmma_gemm<64, false, false><<<dim3(GP, 1), 256, SMEM64>>>(fp_hi, fp_lo,
        Whi + (size_t)22 * 65536, Wlo + (size_t)22 * 65536,
        out_b, (float*)d_out, nullptr, nullptr, NP, 64, 1.f);
}

// round 9
// speedup vs baseline: 1.8964x; 1.3323x over previous
#include <cuda_runtime.h>
#include <cuda_bf16.h>
#include <math.h>
#include <stdint.h>

// ---------------------------------------------------------------------------
// HGT forward. GEMMs via mma.sync bf16 (hi/lo 3-term = fp32-class accuracy).
// R8/R9: 512-thread GEMM CTAs (16 warps, 4x4 warp grid) for latency hiding.
// ---------------------------------------------------------------------------
#define NA     20000
#define NP     40000
#define D      256
#define DOUT   64
#define LL     2
#define E_WB   150000
#define E_W    150000
#define E_C    300000
#define NSLOT  23
// paper proj row: [0,256)=q | [256,512)=k_wb | [512,768)=k_c | [768,1024)=m_wb | [1024,1280)=m_c
#define PSTR   1280
// author proj row: [0,256)=q | [256,512)=k_w | [512,768)=m_w
#define ASTR   768

// ------------------------- device scratch ----------------------------------
__device__ float g_feats_a[2][NA * D];
__device__ float g_feats_p[2][NP * D];
__device__ float g_proj_a[NA * ASTR];
__device__ float g_proj_p[NP * PSTR];
__device__ float g_agg_a[NA * D];
__device__ float g_agg_p[NP * D];
__device__ float g_tr_a[NA * D];
__device__ float g_tr_p[NP * D];
__device__ float g_Wk[LL * 3 * D * D];
__device__ float g_bk[LL * 3 * D];
__device__ float g_Wm[LL * 3 * D * D];
__device__ float g_bm[LL * 3 * D];
__device__ float g_bias_p[LL * PSTR];
__device__ float g_bias_a[LL * ASTR];
// bf16 hi/lo operands
__device__ __nv_bfloat16 g_xa_hi[NA * D], g_xa_lo[NA * D];
__device__ __nv_bfloat16 g_xp_hi[NP * D], g_xp_lo[NP * D];
__device__ __nv_bfloat16 g_fa_hi[NA * D], g_fa_lo[NA * D];
__device__ __nv_bfloat16 g_fp_hi[NP * D], g_fp_lo[NP * D];
__device__ __nv_bfloat16 g_ga_hi[NA * D], g_ga_lo[NA * D];
__device__ __nv_bfloat16 g_gp_hi[NP * D], g_gp_lo[NP * D];
__device__ __nv_bfloat16 g_Whi[NSLOT * D * D], g_Wlo[NSLOT * D * D];

// ------------------------- small helpers -----------------------------------
__device__ __forceinline__ uint32_t smem_u32(const void* p) {
    uint32_t a;
    asm("{ .reg .u64 t; cvta.to.shared.u64 t, %1; cvt.u32.u64 %0, t; }" : "=r"(a) : "l"(p));
    return a;
}
#define SWZ(off) ((off) ^ (((off) >> 3) & 0x70))

#define CPASYNC16(dst, src) \
    asm volatile("cp.async.cg.shared.global [%0], [%1], 16;" :: "r"(dst), "l"(src) : "memory")

#define LDSM_X4(r0, r1, r2, r3, addr)                                         \
    asm volatile("ldmatrix.sync.aligned.m8n8.x4.shared.b16 {%0,%1,%2,%3}, [%4];" \
                 : "=r"(r0), "=r"(r1), "=r"(r2), "=r"(r3) : "r"(addr))

#define MMA16816(d, a, b0, b1)                                                \
    asm volatile("mma.sync.aligned.m16n8k16.row.col.f32.bf16.bf16.f32 "       \
                 "{%0,%1,%2,%3}, {%4,%5,%6,%7}, {%8,%9}, {%0,%1,%2,%3};"      \
                 : "+f"((d)[0]), "+f"((d)[1]), "+f"((d)[2]), "+f"((d)[3])     \
                 : "r"((a)[0]), "r"((a)[1]), "r"((a)[2]), "r"((a)[3]),        \
                   "r"(b0), "r"(b1))

__device__ __forceinline__ float gelu_exact(float x) {
    return 0.5f * x * (1.0f + erff(x * 0.70710678118654752f));
}

// ---------------------------------------------------------------------------
// combine per-head w_att/w_msg into dense K/M projection weights (fp32).
// ---------------------------------------------------------------------------
__global__ void combine_weights(const float* __restrict__ kW, const float* __restrict__ kb,
                                const float* __restrict__ mW, const float* __restrict__ mb,
                                const float* __restrict__ w_att, const float* __restrict__ w_msg,
                                float* __restrict__ Wk, float* __restrict__ bk,
                                float* __restrict__ Wm, float* __restrict__ bm)
{
    int mat = blockIdx.x;
    int l = mat / 6;
    int r6 = mat % 6;
    int e = r6 / 2;
    int which = r6 % 2;
    int d = blockIdx.y;        // 0..256 (256 == bias row)
    int j = threadIdx.x;
    int h = j >> 6;
    int jj = j & 63;
    int st = (e == 1) ? 0 : 1;

    const float* W   = which ? mW : kW;
    const float* B   = which ? mb : kb;
    const float* att = which ? w_msg : w_att;

    const float* wrow;
    if (d < 256) wrow = W + (((size_t)(l * 2 + st) * 256 + d) * 256);
    else         wrow = B + ((size_t)(l * 2 + st) * 256);
    const float* a = att + ((size_t)((l * 3 + e) * 4 + h)) * 64 * 64;

    float s = 0.f;
#pragma unroll 8
    for (int c = 0; c < 64; c++)
        s += wrow[h * 64 + c] * a[c * 64 + jj];

    float* out  = which ? Wm : Wk;
    float* outb = which ? bm : bk;
    if (d < 256) out[((size_t)(l * 3 + e) * 256 + d) * 256 + j] = s;
    else         outb[(size_t)(l * 3 + e) * 256 + j] = s;
}

// ---------------------------------------------------------------------------
// Transpose + split all weight matrices into bf16 hi/lo, K-major [n][k].
// Slot order: 0,1 adapt | 2+l*8+{0..7}: q_p,k_wb,k_c,m_wb,m_c,q_a,k_w,m_w
//             | 18+l*2+nt aW | 22 out_W
// ---------------------------------------------------------------------------
__global__ void transpose_split(const float* __restrict__ adapt_W, const float* __restrict__ qW,
                                const float* __restrict__ Wk, const float* __restrict__ Wm,
                                const float* __restrict__ aW, const float* __restrict__ outW,
                                __nv_bfloat16* __restrict__ Whi, __nv_bfloat16* __restrict__ Wlo)
{
    int slot = blockIdx.z;
    const float* src; int NC = 256;
    if (slot < 2)        src = adapt_W + (size_t)slot * 65536;
    else if (slot < 18) {
        int l = (slot - 2) / 8, o = (slot - 2) % 8;
        switch (o) {
            case 0: src = qW + (size_t)(l * 2 + 1) * 65536; break;
            case 1: src = Wk + (size_t)(l * 3 + 2) * 65536; break;
            case 2: src = Wk + (size_t)(l * 3 + 0) * 65536; break;
            case 3: src = Wm + (size_t)(l * 3 + 2) * 65536; break;
            case 4: src = Wm + (size_t)(l * 3 + 0) * 65536; break;
            case 5: src = qW + (size_t)(l * 2 + 0) * 65536; break;
            case 6: src = Wk + (size_t)(l * 3 + 1) * 65536; break;
            default: src = Wm + (size_t)(l * 3 + 1) * 65536; break;
        }
    }
    else if (slot < 22)  src = aW + (size_t)(slot - 18) * 65536;
    else               { src = outW; NC = 64; }

    int k0 = blockIdx.x * 32, n0 = blockIdx.y * 32;
    if (n0 >= NC) return;
    int tx = threadIdx.x, ty = threadIdx.y;

    __shared__ float t[32][33];
#pragma unroll
    for (int i = 0; i < 4; i++) {
        int k = k0 + ty + i * 8;
        t[ty + i * 8][tx] = src[(size_t)k * NC + n0 + tx];
    }
    __syncthreads();
#pragma unroll
    for (int i = 0; i < 4; i++) {
        int n = n0 + ty + i * 8, k = k0 + tx;
        float v = t[tx][ty + i * 8];
        __nv_bfloat16 h = __float2bfloat16(v);
        float r = v - __bfloat162float(h);
        size_t o = (size_t)slot * 65536 + (size_t)n * 256 + k;
        Whi[o] = h;
        Wlo[o] = __float2bfloat16(r);
    }
}

// ---------------------------------------------------------------------------
// Pack per-layer projection biases into the batched column layout.
// ---------------------------------------------------------------------------
__global__ void pack_bias(const float* __restrict__ qb, const float* __restrict__ bk,
                          const float* __restrict__ bm,
                          float* __restrict__ bp, float* __restrict__ ba)
{
    int idx = blockIdx.x * 256 + threadIdx.x;    // 2 * 2048
    if (idx >= LL * 2048) return;
    int l = idx / 2048, r = idx % 2048;
    int seg = r >> 8, c = r & 255;
    float v;
    switch (seg) {
        case 0: v = qb[(l * 2 + 1) * 256 + c]; break;
        case 1: v = bk[(l * 3 + 2) * 256 + c]; break;
        case 2: v = bk[(l * 3 + 0) * 256 + c]; break;
        case 3: v = bm[(l * 3 + 2) * 256 + c]; break;
        case 4: v = bm[(l * 3 + 0) * 256 + c]; break;
        case 5: v = qb[(l * 2 + 0) * 256 + c]; break;
        case 6: v = bk[(l * 3 + 1) * 256 + c]; break;
        default: v = bm[(l * 3 + 1) * 256 + c]; break;
    }
    if (seg < 5) bp[l * PSTR + seg * 256 + c] = v;
    else         ba[l * ASTR + (seg - 5) * 256 + c] = v;
}

// ---------------------------------------------------------------------------
// fp32 -> bf16 hi/lo split (vectorized).
// ---------------------------------------------------------------------------
__global__ void split_hilo(const float* __restrict__ s, __nv_bfloat16* __restrict__ hi,
                           __nv_bfloat16* __restrict__ lo, int n4)
{
    int i = blockIdx.x * blockDim.x + threadIdx.x;
    if (i >= n4) return;
    float4 v = ((const float4*)s)[i];
    __nv_bfloat16 h[4], l[4];
    float vv[4] = {v.x, v.y, v.z, v.w};
#pragma unroll
    for (int j = 0; j < 4; j++) {
        h[j] = __float2bfloat16(vv[j]);
        l[j] = __float2bfloat16(vv[j] - __bfloat162float(h[j]));
    }
    ((uint2*)hi)[i] = *(uint2*)h;
    ((uint2*)lo)[i] = *(uint2*)l;
}

// ---------------------------------------------------------------------------
// HMMA GEMM: C[M, grid.y*BN] (row stride Ntot) = epi( scale*(A @ W^T) + bias )
// A bf16 hi/lo [M][256] k-contig; W bf16 hi/lo [rows][256] k-contig.
// 3-term: Ahi*Whi + Ahi*Wlo + Alo*Whi, fp32 register accumulation.
// 512 threads = 16 warps (4M x 4N), CTA tile 128 x BN, warp tile 32 x BN/4,
// K chunks of 64, 2-stage cp.async pipeline, SW128 swizzle + ldmatrix.
// ---------------------------------------------------------------------------
#define A_HI_OFF  0
#define A_LO_OFF  16384

template <int BN, bool GELU, bool HILO>
__global__ void __launch_bounds__(512, 1)
hmma_gemm(const __nv_bfloat16* __restrict__ Ahi, const __nv_bfloat16* __restrict__ Alo,
          const __nv_bfloat16* __restrict__ Whi, const __nv_bfloat16* __restrict__ Wlo,
          const float* __restrict__ bias, float* __restrict__ C,
          __nv_bfloat16* __restrict__ Chi, __nv_bfloat16* __restrict__ Clo,
          int M, int Ntot, float scale)
{
    constexpr int WN = BN / 4;          // warp n extent (32 for BN=128, 16 for BN=64)
    constexpr int NT = WN / 16;         // n16 tiles per warp (2 / 1)
    constexpr int B_HI_OFF = 32768;
    constexpr int B_LO_OFF = 32768 + BN * 128;
    constexpr int STG = 32768 + 2 * BN * 128;
    constexpr int A_OPS = 2048;                 // 128 rows * 8 sixteens * (hi+lo)
    constexpr int TOT_OPS = A_OPS + BN * 16;    // + B rows * 8 * (hi+lo)

    extern __shared__ __align__(1024) char sm[];
    const uint32_t sb = smem_u32(sm);

    const int tid = threadIdx.x;
    const int lane = tid & 31, wid = tid >> 5;
    const int wm = wid & 3, wn = wid >> 2;          // warp grid 4 x 4
    const int m0 = blockIdx.x * 128, n0 = blockIdx.y * BN;

    auto load_chunk = [&](int kc, int stg) {
        uint32_t base = sb + stg * STG;
        int kb = kc * 64;
#pragma unroll
        for (int it = tid; it < TOT_OPS; it += 512) {
            bool isA = it < A_OPS;
            int i = isA ? (it & 1023) : ((it - A_OPS) % (BN * 8));
            bool isHi = isA ? (it < 1024) : ((it - A_OPS) < BN * 8);
            int r = i >> 3, s = i & 7;
            uint32_t o = SWZ((uint32_t)(r * 128 + s * 16));
            if (isA) {
                if (m0 + r < M) {
                    const __nv_bfloat16* gp = (isHi ? Ahi : Alo) + (size_t)(m0 + r) * 256 + kb + s * 8;
                    CPASYNC16(base + (isHi ? A_HI_OFF : A_LO_OFF) + o, gp);
                }
            } else {
                const __nv_bfloat16* gp = (isHi ? Whi : Wlo) + (size_t)(n0 + r) * 256 + kb + s * 8;
                CPASYNC16(base + (isHi ? B_HI_OFF : B_LO_OFF) + o, gp);
            }
        }
        asm volatile("cp.async.commit_group;" ::: "memory");
    };

    float d[2][2 * NT][4];
#pragma unroll
    for (int i = 0; i < 2; i++)
#pragma unroll
        for (int j = 0; j < 2 * NT; j++)
#pragma unroll
            for (int r = 0; r < 4; r++) d[i][j][r] = 0.f;

    const int g = lane >> 3, l7 = lane & 7;
    const int a_row_off = (g & 1) ? 8 : 0;
    const int a_byte_off = (g & 2) ? 16 : 0;
    const int b_row_off = (g & 2) ? 8 : 0;
    const int b_byte_off = (g & 1) ? 16 : 0;

    load_chunk(0, 0);

    for (int kc = 0; kc < 4; kc++) {
        if (kc < 3) load_chunk(kc + 1, (kc + 1) & 1);
        if (kc < 3) asm volatile("cp.async.wait_group 1;" ::: "memory");
        else        asm volatile("cp.async.wait_group 0;" ::: "memory");
        __syncthreads();

        uint32_t base = sb + (kc & 1) * STG;
#pragma unroll
        for (int kk = 0; kk < 4; kk++) {
            int kb2 = kk * 32;
            uint32_t a_hi[2][4], a_lo[2][4], b_hi[NT][4], b_lo[NT][4];
#pragma unroll
            for (int i = 0; i < 2; i++) {
                uint32_t o = SWZ((uint32_t)((wm * 32 + i * 16 + l7 + a_row_off) * 128 + kb2 + a_byte_off));
                LDSM_X4(a_hi[i][0], a_hi[i][1], a_hi[i][2], a_hi[i][3], base + A_HI_OFF + o);
                LDSM_X4(a_lo[i][0], a_lo[i][1], a_lo[i][2], a_lo[i][3], base + A_LO_OFF + o);
            }
#pragma unroll
            for (int jt = 0; jt < NT; jt++) {
                uint32_t o = SWZ((uint32_t)((wn * WN + jt * 16 + l7 + b_row_off) * 128 + kb2 + b_byte_off));
                LDSM_X4(b_hi[jt][0], b_hi[jt][1], b_hi[jt][2], b_hi[jt][3], base + B_HI_OFF + o);
                LDSM_X4(b_lo[jt][0], b_lo[jt][1], b_lo[jt][2], b_lo[jt][3], base + B_LO_OFF + o);
            }
#pragma unroll
            for (int i = 0; i < 2; i++)
#pragma unroll
                for (int jt = 0; jt < NT; jt++)
#pragma unroll
                    for (int half = 0; half < 2; half++) {
                        int j = jt * 2 + half, sel = half * 2;
                        MMA16816(d[i][j], a_hi[i], b_hi[jt][sel], b_hi[jt][sel + 1]);
                        MMA16816(d[i][j], a_hi[i], b_lo[jt][sel], b_lo[jt][sel + 1]);
                        MMA16816(d[i][j], a_lo[i], b_hi[jt][sel], b_hi[jt][sel + 1]);
                    }
        }
        __syncthreads();
    }

    // ---- epilogue ----
    const int r_base = m0 + wm * 32;
    const int c_base = n0 + wn * WN;
#pragma unroll
    for (int i = 0; i < 2; i++)
#pragma unroll
        for (int j = 0; j < 2 * NT; j++) {
            int col = c_base + j * 8 + (lane & 3) * 2;
            float2 b2 = *(const float2*)(bias + col);
#pragma unroll
            for (int half = 0; half < 2; half++) {
                int row = r_base + i * 16 + (lane >> 2) + half * 8;
                if (row >= M) continue;
                float vx = d[i][j][half * 2 + 0] * scale + b2.x;
                float vy = d[i][j][half * 2 + 1] * scale + b2.y;
                if (GELU) { vx = gelu_exact(vx); vy = gelu_exact(vy); }
                *(float2*)(C + (size_t)row * Ntot + col) = make_float2(vx, vy);
                if (HILO) {
                    union { __nv_bfloat16 b[2]; uint32_t u; } uh, ul;
                    uh.b[0] = __float2bfloat16(vx);
                    uh.b[1] = __float2bfloat16(vy);
                    ul.b[0] = __float2bfloat16(vx - __bfloat162float(uh.b[0]));
                    ul.b[1] = __float2bfloat16(vy - __bfloat162float(uh.b[1]));
                    *(uint32_t*)(Chi + (size_t)row * Ntot + col) = uh.u;
                    *(uint32_t*)(Clo + (size_t)row * Ntot + col) = ul.u;
                }
            }
        }
}

// ---------------------------------------------------------------------------
// Edge kernel: one warp per edge; q/k/m read from strided projection buffers.
// ---------------------------------------------------------------------------
__global__ void edge_kernel(const float* __restrict__ q, int qs,
                            const float* __restrict__ khat, const float* __restrict__ mhat, int kms,
                            const int* __restrict__ src, const int* __restrict__ dst,
                            const float* __restrict__ ew, const float* __restrict__ pri,
                            float* __restrict__ agg, int E)
{
    int gw = (int)((blockIdx.x * (size_t)blockDim.x + threadIdx.x) >> 5);
    int lane = threadIdx.x & 31;
    if (gw >= E) return;

    int s = src[gw];
    int d = dst[gw];

    const float4* qr = (const float4*)(q    + (size_t)d * qs) + lane * 2;
    const float4* kr = (const float4*)(khat + (size_t)s * kms) + lane * 2;
    float4 q0 = qr[0], q1 = qr[1];
    float4 k0 = kr[0], k1 = kr[1];
    float p = q0.x * k0.x + q0.y * k0.y + q0.z * k0.z + q0.w * k0.w
            + q1.x * k1.x + q1.y * k1.y + q1.z * k1.z + q1.w * k1.w;
    p += __shfl_xor_sync(0xffffffffu, p, 1);
    p += __shfl_xor_sync(0xffffffffu, p, 2);
    p += __shfl_xor_sync(0xffffffffu, p, 4);

    int h = lane >> 3;
    float score = p * pri[h] * 0.125f;
    float attn = ew[gw] / (1.f + __expf(-score));

    const float4* mr = (const float4*)(mhat + (size_t)s * kms) + lane * 2;
    float4 m0 = mr[0], m1 = mr[1];

    float* out = agg + (size_t)d * 256 + lane * 8;
    asm volatile("red.global.add.v4.f32 [%0], {%1,%2,%3,%4};" ::
                 "l"(out), "f"(m0.x * attn), "f"(m0.y * attn),
                 "f"(m0.z * attn), "f"(m0.w * attn) : "memory");
    asm volatile("red.global.add.v4.f32 [%0], {%1,%2,%3,%4};" ::
                 "l"(out + 4), "f"(m1.x * attn), "f"(m1.y * attn),
                 "f"(m1.z * attn), "f"(m1.w * attn) : "memory");
}

// ---------------------------------------------------------------------------
// Skip-blend + LayerNorm; also emits bf16 hi/lo of the output.
// ---------------------------------------------------------------------------
__global__ void ln_blend_kernel(const float* __restrict__ tr, const float* __restrict__ feats,
                                const float* __restrict__ g, const float* __restrict__ b,
                                const float* __restrict__ skip, int skip_idx,
                                float* __restrict__ out,
                                __nv_bfloat16* __restrict__ ohi, __nv_bfloat16* __restrict__ olo,
                                int N)
{
    int row = (int)((blockIdx.x * (size_t)blockDim.x + threadIdx.x) >> 5);
    int lane = threadIdx.x & 31;
    if (row >= N) return;

    float alpha = 1.f / (1.f + __expf(-skip[skip_idx]));
    float beta = 1.f - alpha;

    const float4* t4 = (const float4*)(tr    + (size_t)row * 256) + lane * 2;
    const float4* f4 = (const float4*)(feats + (size_t)row * 256) + lane * 2;
    float4 ta = t4[0], tb = t4[1], fa = f4[0], fb = f4[1];

    float v[8];
    v[0] = ta.x * alpha + fa.x * beta;  v[1] = ta.y * alpha + fa.y * beta;
    v[2] = ta.z * alpha + fa.z * beta;  v[3] = ta.w * alpha + fa.w * beta;
    v[4] = tb.x * alpha + fb.x * beta;  v[5] = tb.y * alpha + fb.y * beta;
    v[6] = tb.z * alpha + fb.z * beta;  v[7] = tb.w * alpha + fb.w * beta;

    float s = 0.f;
#pragma unroll
    for (int i = 0; i < 8; i++) s += v[i];
#pragma unroll
    for (int o = 16; o > 0; o >>= 1) s += __shfl_xor_sync(0xffffffffu, s, o);
    float mean = s * (1.f / 256.f);

    float sq = 0.f;
#pragma unroll
    for (int i = 0; i < 8; i++) { float dv = v[i] - mean; sq += dv * dv; }
#pragma unroll
    for (int o = 16; o > 0; o >>= 1) sq += __shfl_xor_sync(0xffffffffu, sq, o);
    float rstd = rsqrtf(sq * (1.f / 256.f) + 1e-5f);

    const float4* g4 = (const float4*)(g) + lane * 2;
    const float4* b4 = (const float4*)(b) + lane * 2;
    float4 ga = g4[0], gb = g4[1], ba = b4[0], bb = b4[1];
    float gg[8] = {ga.x, ga.y, ga.z, ga.w, gb.x, gb.y, gb.z, gb.w};
    float bbv[8] = {ba.x, ba.y, ba.z, ba.w, bb.x, bb.y, bb.z, bb.w};

    float o8[8];
    union { __nv_bfloat16 b[8]; uint4 u; } uh, ul;
#pragma unroll
    for (int i = 0; i < 8; i++) {
        o8[i] = (v[i] - mean) * rstd * gg[i] + bbv[i];
        uh.b[i] = __float2bfloat16(o8[i]);
        ul.b[i] = __float2bfloat16(o8[i] - __bfloat162float(uh.b[i]));
    }

    float4* outp = (float4*)(out + (size_t)row * 256) + lane * 2;
    outp[0] = make_float4(o8[0], o8[1], o8[2], o8[3]);
    outp[1] = make_float4(o8[4], o8[5], o8[6], o8[7]);
    *(uint4*)(ohi + (size_t)row * 256 + lane * 8) = uh.u;
    *(uint4*)(olo + (size_t)row * 256 + lane * 8) = ul.u;
}

// ---------------------------------------------------------------------------
// Host orchestration.
// ---------------------------------------------------------------------------
static const int SMEM128 = 2 * (32768 + 2 * 128 * 128);   // 131072
static const int SMEM64  = 2 * (32768 + 2 * 64 * 128);    // 98304

extern "C" void kernel_launch(void* const* d_in, const int* in_sizes, int n_in,
                              void* d_out, int out_size)
{
    const float* x_author = (const float*)d_in[0];
    const float* x_paper  = (const float*)d_in[1];
    const float* ew_wb    = (const float*)d_in[2];
    const float* ew_w     = (const float*)d_in[3];
    const float* ew_c     = (const float*)d_in[4];
    const float* adapt_W  = (const float*)d_in[5];
    const float* adapt_b  = (const float*)d_in[6];
    const float* kW       = (const float*)d_in[7];
    const float* kb       = (const float*)d_in[8];
    const float* qW       = (const float*)d_in[9];
    const float* qb       = (const float*)d_in[10];
    const float* mW       = (const float*)d_in[11];
    const float* mb       = (const float*)d_in[12];
    const float* aW       = (const float*)d_in[13];
    const float* ab       = (const float*)d_in[14];
    const float* w_pri    = (const float*)d_in[15];
    const float* w_att    = (const float*)d_in[16];
    const float* w_msg    = (const float*)d_in[17];
    const float* skip     = (const float*)d_in[18];
    const float* ln_g     = (const float*)d_in[19];
    const float* ln_b     = (const float*)d_in[20];
    const float* out_W    = (const float*)d_in[21];
    const float* out_b    = (const float*)d_in[22];
    const int* src_wb     = (const int*)d_in[23];
    const int* dst_wb     = (const int*)d_in[24];
    const int* src_w      = (const int*)d_in[25];
    const int* dst_w      = (const int*)d_in[26];
    const int* src_c      = (const int*)d_in[27];
    const int* dst_c      = (const int*)d_in[28];
    (void)in_sizes; (void)n_in; (void)out_size;

    cudaFuncSetAttribute(hmma_gemm<128, false, false>, cudaFuncAttributeMaxDynamicSharedMemorySize, SMEM128);
    cudaFuncSetAttribute(hmma_gemm<128, true, true>,   cudaFuncAttributeMaxDynamicSharedMemorySize, SMEM128);
    cudaFuncSetAttribute(hmma_gemm<64, false, false>,  cudaFuncAttributeMaxDynamicSharedMemorySize, SMEM64);

    float *feats_a, *feats_p, *proj_a, *proj_p;
    float *agg_a, *agg_p, *tr_a, *tr_p, *Wkp, *bkp, *Wmp, *bmp, *bias_p, *bias_a;
    __nv_bfloat16 *xa_hi, *xa_lo, *xp_hi, *xp_lo, *fa_hi, *fa_lo, *fp_hi, *fp_lo;
    __nv_bfloat16 *ga_hi, *ga_lo, *gp_hi, *gp_lo, *Whi, *Wlo;
#define SYM(var, sym) cudaGetSymbolAddress((void**)&var, sym)
    SYM(feats_a, g_feats_a); SYM(feats_p, g_feats_p);
    SYM(proj_a, g_proj_a); SYM(proj_p, g_proj_p);
    SYM(agg_a, g_agg_a); SYM(agg_p, g_agg_p);
    SYM(tr_a, g_tr_a); SYM(tr_p, g_tr_p);
    SYM(Wkp, g_Wk); SYM(bkp, g_bk); SYM(Wmp, g_Wm); SYM(bmp, g_bm);
    SYM(bias_p, g_bias_p); SYM(bias_a, g_bias_a);
    SYM(xa_hi, g_xa_hi); SYM(xa_lo, g_xa_lo); SYM(xp_hi, g_xp_hi); SYM(xp_lo, g_xp_lo);
    SYM(fa_hi, g_fa_hi); SYM(fa_lo, g_fa_lo); SYM(fp_hi, g_fp_hi); SYM(fp_lo, g_fp_lo);
    SYM(ga_hi, g_ga_hi); SYM(ga_lo, g_ga_lo); SYM(gp_hi, g_gp_hi); SYM(gp_lo, g_gp_lo);
    SYM(Whi, g_Whi); SYM(Wlo, g_Wlo);
#undef SYM

    float* fa[2] = {feats_a, feats_a + (size_t)NA * D};
    float* fp[2] = {feats_p, feats_p + (size_t)NP * D};

    const int GA = (NA + 127) / 128;   // 157
    const int GP = (NP + 127) / 128;   // 313

    // 0) weight prep
    combine_weights<<<dim3(12, 257), 256>>>(kW, kb, mW, mb, w_att, w_msg, Wkp, bkp, Wmp, bmp);
    transpose_split<<<dim3(8, 8, NSLOT), dim3(32, 8)>>>(adapt_W, qW, Wkp, Wmp, aW, out_W, Whi, Wlo);
    pack_bias<<<(LL * 2048 + 255) / 256, 256>>>(qb, bkp, bmp, bias_p, bias_a);

    // 1) split inputs, adapt + GELU (emits feats fp32 + hi/lo)
    split_hilo<<<(NA * D / 4 + 255) / 256, 256>>>(x_author, xa_hi, xa_lo, NA * D / 4);
    split_hilo<<<(NP * D / 4 + 255) / 256, 256>>>(x_paper, xp_hi, xp_lo, NP * D / 4);
    hmma_gemm<128, true, true><<<dim3(GA, 2), 512, SMEM128>>>(xa_hi, xa_lo, Whi, Wlo,
        adapt_b, fa[0], fa_hi, fa_lo, NA, 256, 1.f);
    hmma_gemm<128, true, true><<<dim3(GP, 2), 512, SMEM128>>>(xp_hi, xp_lo, Whi + 65536, Wlo + 65536,
        adapt_b + 256, fp[0], fp_hi, fp_lo, NP, 256, 1.f);

    for (int l = 0; l < LL; l++) {
        int cur = l & 1, nxt = 1 - cur;

        // batched projections: paper 5 mats (q, k_wb, k_c, m_wb, m_c), author 3 (q, k_w, m_w)
        const size_t psl = (size_t)(2 + l * 8) * 65536;
        const size_t asl = (size_t)(2 + l * 8 + 5) * 65536;
        hmma_gemm<128, false, false><<<dim3(GP, PSTR / 128), 512, SMEM128>>>(fp_hi, fp_lo,
            Whi + psl, Wlo + psl, bias_p + l * PSTR, proj_p, nullptr, nullptr, NP, PSTR, 1.f);
        hmma_gemm<128, false, false><<<dim3(GA, ASTR / 128), 512, SMEM128>>>(fa_hi, fa_lo,
            Whi + asl, Wlo + asl, bias_a + l * ASTR, proj_a, nullptr, nullptr, NA, ASTR, 1.f);

        cudaMemsetAsync(agg_a, 0, (size_t)NA * D * sizeof(float), 0);
        cudaMemsetAsync(agg_p, 0, (size_t)NP * D * sizeof(float), 0);

        // WRITTEN_BY: dst author (q in proj_a), src paper (k/m in proj_p)
        edge_kernel<<<(E_WB + 7) / 8, 256>>>(proj_a, ASTR, proj_p + 256, proj_p + 768, PSTR,
            src_wb, dst_wb, ew_wb, w_pri + (l * 3 + 2) * 4, agg_a, E_WB);
        // WRITES: dst paper, src author
        edge_kernel<<<(E_W + 7) / 8, 256>>>(proj_p, PSTR, proj_a + 256, proj_a + 512, ASTR,
            src_w, dst_w, ew_w, w_pri + (l * 3 + 1) * 4, agg_p, E_W);
        // CITES: dst paper, src paper
        edge_kernel<<<(E_C + 7) / 8, 256>>>(proj_p, PSTR, proj_p + 512, proj_p + 1024, PSTR,
            src_c, dst_c, ew_c, w_pri + (l * 3 + 0) * 4, agg_p, E_C);

        // agg -> hi/lo, then a-projection (0.5 cross-relation mean via scale)
        split_hilo<<<(NA * D / 4 + 255) / 256, 256>>>(agg_a, ga_hi, ga_lo, NA * D / 4);
        split_hilo<<<(NP * D / 4 + 255) / 256, 256>>>(agg_p, gp_hi, gp_lo, NP * D / 4);
        const size_t aa = (size_t)(18 + l * 2 + 0) * 65536;
        const size_t ap = (size_t)(18 + l * 2 + 1) * 65536;
        hmma_gemm<128, false, false><<<dim3(GA, 2), 512, SMEM128>>>(ga_hi, ga_lo,
            Whi + aa, Wlo + aa, ab + (l * 2 + 0) * 256, tr_a, nullptr, nullptr, NA, 256, 1.0f);
        hmma_gemm<128, false, false><<<dim3(GP, 2), 512, SMEM128>>>(gp_hi, gp_lo,
            Whi + ap, Wlo + ap, ab + (l * 2 + 1) * 256, tr_p, nullptr, nullptr, NP, 256, 0.5f);

        // skip blend + LN (emits fp32 feats + hi/lo for next layer / out proj)
        ln_blend_kernel<<<(NA + 7) / 8, 256>>>(tr_a, fa[cur], ln_g + (l * 2 + 0) * 256,
            ln_b + (l * 2 + 0) * 256, skip, l * 3 + 0, fa[nxt], fa_hi, fa_lo, NA);
        ln_blend_kernel<<<(NP + 7) / 8, 256>>>(tr_p, fp[cur], ln_g + (l * 2 + 1) * 256,
            ln_b + (l * 2 + 1) * 256, skip, l * 3 + 1, fp[nxt], fp_hi, fp_lo, NP);
    }

    // output projection: paper feats (hi/lo from last LN) @ out_W + out_b
    hmma_gemm<64, false, false><<<dim3(GP, 1), 512, SMEM64>>>(fp_hi, fp_lo,
        Whi + (size_t)22 * 65536, Wlo + (size_t)22 * 65536,
        out_b, (float*)d_out, nullptr, nullptr, NP, 64, 1.f);
}